// round 9
// baseline (speedup 1.0000x reference)
#include <cuda_runtime.h>
#include <cuda_fp16.h>
#include <stdint.h>
#include <math.h>

#define Bsz 512
#define Tsz 128
#define Hsz 512
#define Vsz 512
#define NBT 65536
#define G4  2048

// ---------------- device scratch ----------------
__device__ __align__(128) __half g_inp[(size_t)NBT*Hsz];
__device__ __align__(128) __half g_seq[(size_t)NBT*Hsz];
__device__ __align__(128) __half g_xgT[(size_t)Tsz*G4*Bsz];   // [t][n][b] fp16
__device__ __align__(128) __half g_h0[Bsz*Hsz], g_h1[Bsz*Hsz];
__device__ __align__(128) float  g_c[Bsz*Hsz];
__device__ __align__(128) __half g_Wih[2*(size_t)G4*Hsz];
__device__ __align__(128) __half g_Whh[2*(size_t)G4*Hsz];
__device__ __align__(128) __half g_dW[(size_t)Vsz*Hsz];
__device__ unsigned g_gen[4], g_cnt[4];

// ---------------- helpers ----------------
__device__ __forceinline__ uint32_t smem_u32(const void* p){
    uint32_t a; asm("{ .reg .u64 t; cvta.to.shared.u64 t, %1; cvt.u32.u64 %0, t; }" : "=r"(a) : "l"(p)); return a;
}
#define CP16(dst, src) asm volatile("cp.async.cg.shared.global [%0], [%1], 16;" :: "r"(dst), "l"(src))
#define CPCOMMIT()     asm volatile("cp.async.commit_group;" ::: "memory")
#define CPWAIT(n)      asm volatile("cp.async.wait_group %0;" :: "n"(n) : "memory")
#define LDSM4(r, a) asm volatile("ldmatrix.sync.aligned.m8n8.x4.shared.b16 {%0,%1,%2,%3}, [%4];" \
    : "=r"((r)[0]),"=r"((r)[1]),"=r"((r)[2]),"=r"((r)[3]) : "r"(a))

__device__ __forceinline__ void mma16816(float* d, const uint32_t* a, const uint32_t* b){
    asm volatile("mma.sync.aligned.m16n8k16.row.col.f32.f16.f16.f32 "
        "{%0,%1,%2,%3}, {%4,%5,%6,%7}, {%8,%9}, {%0,%1,%2,%3};"
        : "+f"(d[0]), "+f"(d[1]), "+f"(d[2]), "+f"(d[3])
        : "r"(a[0]), "r"(a[1]), "r"(a[2]), "r"(a[3]), "r"(b[0]), "r"(b[1]));
}

// ============ generic FF GEMM (fp16 operands, fp32 accum) ============
// BK=64: chunk = 128 rows x 64 fp16 (32 words, padded to 36). A then B.
#define CHW 4608
#define STW 9216
#define SMEMB 110592   // 3 stages

__device__ __forceinline__ void load_chunk(uint32_t sbase,
    const __half* __restrict__ A, const __half* __restrict__ B,
    int m0, int n0, int ck, int bmap, int tid)
{
    #pragma unroll
    for (int i = tid; i < 1024; i += 256) {
        int r = i >> 3, q = i & 7;
        CP16(sbase + (r*36 + q*4)*4, A + (size_t)(m0 + r)*Hsz + ck*64 + q*8);
    }
    #pragma unroll
    for (int i = tid; i < 1024; i += 256) {
        int r = i >> 3, q = i & 7;
        int brow;
        if (bmap == 0)      brow = n0 + r;
        else                { int c = n0 + r; brow = (c & 511)*Tsz + (c >> 9); }
        CP16(sbase + (CHW + r*36 + q*4)*4, B + (size_t)brow*Hsz + ck*64 + q*8);
    }
    CPCOMMIT();
}

__device__ __forceinline__ void compute_chunk(uint32_t stg,
    float acc[4][4][4], int lane, int wm, int wn)
{
    int laneA_r = lane & 15;
    int laneA_c = (lane >> 4) * 4;
    int laneB_r = (lane & 7) + ((lane >> 4) << 3);
    int laneB_c = ((lane >> 3) & 1) * 4;
    #pragma unroll
    for (int ks = 0; ks < 4; ks++) {
        int kw = ks*8;
        uint32_t ah[4][4], bh[2][4];
        #pragma unroll
        for (int mt = 0; mt < 4; mt++) {
            uint32_t aw = (uint32_t)(wm*64 + mt*16 + laneA_r)*36 + kw + laneA_c;
            LDSM4(ah[mt], stg + aw*4);
        }
        #pragma unroll
        for (int np = 0; np < 2; np++) {
            uint32_t bw = (uint32_t)(wn*32 + np*16 + laneB_r)*36 + kw + laneB_c;
            LDSM4(bh[np], stg + (CHW + bw)*4);
        }
        #pragma unroll
        for (int mt = 0; mt < 4; mt++)
        #pragma unroll
        for (int nt = 0; nt < 4; nt++)
            mma16816(acc[mt][nt], ah[mt], &bh[nt>>1][(nt&1)*2]);
    }
}

__global__ void __launch_bounds__(256,2)
gemm_mma(const __half* __restrict__ A, const __half* __restrict__ B,
         const float* __restrict__ br1, const float* __restrict__ br2,
         const float* __restrict__ bcn, void* __restrict__ Cv,
         int Ntot, int bmap, int mx, int cmode)
{
    extern __shared__ uint32_t sm[];
    uint32_t sbase = smem_u32(sm);
    int tid = threadIdx.x, lane = tid & 31, wid = tid >> 5;
    int wm = wid >> 2, wn = wid & 3;
    int bm = mx ? blockIdx.x : blockIdx.y;
    int bn = mx ? blockIdx.y : blockIdx.x;
    int m0 = bm*128, n0 = bn*128;

    float acc[4][4][4];
    #pragma unroll
    for (int a = 0; a < 4; a++)
    #pragma unroll
    for (int b = 0; b < 4; b++)
    #pragma unroll
    for (int cc = 0; cc < 4; cc++) acc[a][b][cc] = 0.f;

    load_chunk(sbase, A, B, m0, n0, 0, bmap, tid);
    int st = 0, nst = 1;
    for (int k = 0; k < 8; k++) {
        if (k < 7) {
            load_chunk(sbase + nst*STW*4, A, B, m0, n0, k+1, bmap, tid);
            CPWAIT(1);
        } else {
            CPWAIT(0);
        }
        __syncthreads();
        compute_chunk(sbase + st*STW*4, acc, lane, wm, wn);
        st = nst; nst = (nst + 1 == 3) ? 0 : nst + 1;
    }

    #pragma unroll
    for (int mt = 0; mt < 4; mt++) {
        #pragma unroll
        for (int half = 0; half < 2; half++) {
            int m = m0 + wm*64 + mt*16 + (lane >> 2) + half*8;
            float rb = br1 ? (br1[m] + br2[m]) : 0.f;
            #pragma unroll
            for (int nt = 0; nt < 4; nt++) {
                int c = n0 + wn*32 + nt*8 + (lane & 3)*2;
                float v0 = acc[mt][nt][half*2+0] + rb;
                float v1 = acc[mt][nt][half*2+1] + rb;
                if (bcn) { v0 += bcn[c]; v1 += bcn[c+1]; }
                if (cmode) {
                    __half* dst = (__half*)Cv + ((size_t)(c >> 9)*G4 + m)*Bsz + (c & 511);
                    __half2 hv; hv.x = __float2half_rn(v0); hv.y = __float2half_rn(v1);
                    *(__half2*)dst = hv;
                } else {
                    *(float2*)((float*)Cv + (size_t)m*Ntot + c) = make_float2(v0, v1);
                }
            }
        }
    }
}

// ============ persistent LSTM recurrence (fp16, single-shot h load) ============
// grid (32,4): x -> 16 units (u0), y -> 128 batch (b0). Group barrier per y.
// SMEM: W 8ck x 64r x 36w = 18432 w (73728B); H full 8ck x 128r x 36w = 36864 w (147456B)
#define PS_SMEM 221184
__device__ __forceinline__ int WOFFf(int ck,int r){ return (ck*64 + r)*36; }
__device__ __forceinline__ int HOFFf(int ck,int r){ return 18432 + (ck*128 + r)*36; }

__global__ void reset_bar(){ int i = threadIdx.x; if (i < 4) { g_gen[i] = 0; g_cnt[i] = 0; } }

__global__ void __launch_bounds__(256,1)
lstm_persist(const __half* __restrict__ xg, const __half* __restrict__ W,
             __half* __restrict__ h0, __half* __restrict__ h1,
             float* __restrict__ cst, __half* __restrict__ seq)
{
    extern __shared__ uint32_t sm[];
    uint32_t sb = smem_u32(sm);
    int tid = threadIdx.x, lane = tid & 31, w = tid >> 5;
    int laneR = lane >> 2, laneC = lane & 3;
    int u0 = blockIdx.x * 16;
    int b0 = blockIdx.y * 128;
    int gid = blockIdx.y;
    unsigned nGrp = gridDim.x;

    int laneA_r = lane & 15;
    int laneA_c = (lane >> 4) * 4;
    int laneB_r = (lane & 7) + ((lane >> 4) << 3);
    int laneB_c = ((lane >> 3) & 1) * 4;

    // ---- persistent W tile: rows n = g*16+ul -> Whh row g*512 + u0+ul ----
    for (int i = tid; i < 4096; i += 256) {
        int ck = i >> 9, rem = i & 511;
        int r = rem >> 3, q = rem & 7;
        int g = r >> 4, ul = r & 15;
        CP16(sb + (WOFFf(ck,r) + q*4)*4,
             W + ((size_t)(g*Hsz + u0 + ul))*Hsz + ck*64 + q*8);
    }
    CPCOMMIT(); CPWAIT(0);
    __syncthreads();

    __half* hb[2] = {h0, h1};

    for (int t = 0; t < Tsz; t++) {
        const __half* Hc = hb[t & 1];
        __half* Nx = hb[(t+1) & 1];

        // issue ALL h loads for this step at once (skip at t=0: h=0)
        if (t > 0) {
            #pragma unroll
            for (int i = tid; i < 8192; i += 256) {
                int ck = i >> 10, rem = i & 1023;
                int r = rem >> 3, q = rem & 7;
                CP16(sb + (HOFFf(ck,r) + q*4)*4,
                     Hc + (size_t)(b0 + r)*Hsz + ck*64 + q*8);
            }
            CPCOMMIT();
        }

        // xg prefetch overlaps the cp.async fill
        float xv[2][16];
        {
            const __half* xgt = xg + (size_t)t*G4*Bsz;
            #pragma unroll
            for (int half = 0; half < 2; half++) {
                int b = b0 + w*16 + laneR + half*8;
                #pragma unroll
                for (int uh = 0; uh < 2; uh++)
                #pragma unroll
                for (int du = 0; du < 2; du++) {
                    int u = u0 + laneC*2 + uh*8 + du;
                    #pragma unroll
                    for (int g = 0; g < 4; g++)
                        xv[half][uh*8 + du*4 + g] =
                            __half2float(xgt[((size_t)(g*Hsz + u))*Bsz + b]);
                }
            }
        }

        float acc[8][4];
        #pragma unroll
        for (int i = 0; i < 8; i++)
        #pragma unroll
        for (int j = 0; j < 4; j++) acc[i][j] = 0.f;

        if (t > 0) {
            CPWAIT(0);
            __syncthreads();
            for (int ck = 0; ck < 8; ck++) {
                #pragma unroll
                for (int ks = 0; ks < 4; ks++) {
                    int kw = ks*8;
                    uint32_t ah[4], bh[4][4];
                    uint32_t aw = (uint32_t)(HOFFf(ck, w*16 + laneA_r)) + kw + laneA_c;
                    LDSM4(ah, sb + aw*4);
                    #pragma unroll
                    for (int np = 0; np < 4; np++) {
                        uint32_t bw = (uint32_t)(WOFFf(ck, np*16 + laneB_r)) + kw + laneB_c;
                        LDSM4(bh[np], sb + bw*4);
                    }
                    #pragma unroll
                    for (int nt = 0; nt < 8; nt++)
                        mma16816(acc[nt], ah, &bh[nt>>1][(nt&1)*2]);
                }
            }
        }

        // epilogue: gates + state update (c=0 at t=0)
        #pragma unroll
        for (int half = 0; half < 2; half++) {
            int b = b0 + w*16 + laneR + half*8;
            #pragma unroll
            for (int uh = 0; uh < 2; uh++) {
                float cn[2], hn[2];
                #pragma unroll
                for (int du = 0; du < 2; du++) {
                    int q = half*2 + du;
                    float gi = acc[0*2+uh][q] + xv[half][uh*8+du*4+0];
                    float gf = acc[1*2+uh][q] + xv[half][uh*8+du*4+1];
                    float gg = acc[2*2+uh][q] + xv[half][uh*8+du*4+2];
                    float go = acc[3*2+uh][q] + xv[half][uh*8+du*4+3];
                    float is = 1.f/(1.f + __expf(-gi));
                    float fs = 1.f/(1.f + __expf(-gf));
                    float os = 1.f/(1.f + __expf(-go));
                    float gt = tanhf(gg);
                    int u = u0 + laneC*2 + uh*8 + du;
                    float co = (t > 0) ? cst[(size_t)b*Hsz + u] : 0.f;
                    cn[du] = fs*co + is*gt;
                    hn[du] = os*tanhf(cn[du]);
                }
                int u2 = u0 + laneC*2 + uh*8;
                size_t so = (size_t)b*Hsz + u2;
                *(float2*)(cst + so) = make_float2(cn[0], cn[1]);
                __half2 hp;
                hp.x = __float2half_rn(hn[0]);
                hp.y = __float2half_rn(hn[1]);
                *(__half2*)(Nx + so) = hp;
                *(__half2*)(seq + ((size_t)b*Tsz + t)*Hsz + u2) = hp;
            }
        }

        // ---- per-group grid barrier (32 CTAs sharing b0) ----
        if (t < Tsz - 1) {
            __threadfence();
            __syncthreads();
            if (tid == 0) {
                unsigned target = (unsigned)(t + 1);
                if (atomicAdd(&g_cnt[gid], 1u) == nGrp - 1u) {
                    atomicExch(&g_cnt[gid], 0u);
                    __threadfence();
                    atomicAdd(&g_gen[gid], 1u);
                } else {
                    unsigned v;
                    do { asm volatile("ld.acquire.gpu.global.u32 %0, [%1];" : "=r"(v) : "l"(&g_gen[gid])); }
                    while (v < target);
                }
            }
            __syncthreads();
            __threadfence();
        }
    }
}

// ---------------- small kernels ----------------
__global__ void conv_kernel(const float* __restrict__ s, __half* __restrict__ h, int n4){
    int i = blockIdx.x*blockDim.x + threadIdx.x;
    if (i < n4) {
        float4 v = ((const float4*)s)[i];
        __half2 a, b;
        a.x = __float2half_rn(v.x); a.y = __float2half_rn(v.y);
        b.x = __float2half_rn(v.z); b.y = __float2half_rn(v.w);
        ((__half2*)h)[i*2]   = a;
        ((__half2*)h)[i*2+1] = b;
    }
}
__global__ void embed_kernel(const int* __restrict__ x, const float* __restrict__ y,
                             const float* __restrict__ emb, const float* __restrict__ yW,
                             const float* __restrict__ yb, __half* __restrict__ o){
    int bt = blockIdx.x;            // bt = t*512 + b
    int t = bt >> 9, b = bt & 511;
    int h4 = threadIdx.x;           // 128 threads x 4 elems
    int tok = (t == 0) ? Vsz : x[b*Tsz + t - 1];
    float4 e = ((const float4*)(emb + (size_t)tok*Hsz))[h4];
    float4 wv = ((const float4*)yW)[h4];
    float4 bv = ((const float4*)yb)[h4];
    float yy = y[b];
    __half2 a, c;
    a.x = __float2half_rn(e.x + yy*wv.x + bv.x);
    a.y = __float2half_rn(e.y + yy*wv.y + bv.y);
    c.x = __float2half_rn(e.z + yy*wv.z + bv.z);
    c.y = __float2half_rn(e.w + yy*wv.w + bv.w);
    ((__half2*)(o + (size_t)bt*Hsz))[h4*2]   = a;
    ((__half2*)(o + (size_t)bt*Hsz))[h4*2+1] = c;
}

// ---------------- launch ----------------
extern "C" void kernel_launch(void* const* d_in, const int* in_sizes, int n_in,
                              void* d_out, int out_size)
{
    const int*   x    = (const int*)  d_in[0];
    const float* y    = (const float*)d_in[1];
    const float* emb  = (const float*)d_in[2];
    const float* yW   = (const float*)d_in[3];
    const float* yb   = (const float*)d_in[4];
    const float* Wih  = (const float*)d_in[5];
    const float* Whh  = (const float*)d_in[6];
    const float* bih  = (const float*)d_in[7];
    const float* bhh  = (const float*)d_in[8];
    const float* decW = (const float*)d_in[9];
    const float* decb = (const float*)d_in[10];
    float* out = (float*)d_out;

    __half *inp, *seq, *Wih_c, *Whh_c, *dW_c, *h0, *h1, *xgT;
    float *c;
    cudaGetSymbolAddress((void**)&inp,   g_inp);
    cudaGetSymbolAddress((void**)&seq,   g_seq);
    cudaGetSymbolAddress((void**)&xgT,   g_xgT);
    cudaGetSymbolAddress((void**)&h0,    g_h0);
    cudaGetSymbolAddress((void**)&h1,    g_h1);
    cudaGetSymbolAddress((void**)&c,     g_c);
    cudaGetSymbolAddress((void**)&Wih_c, g_Wih);
    cudaGetSymbolAddress((void**)&Whh_c, g_Whh);
    cudaGetSymbolAddress((void**)&dW_c,  g_dW);

    cudaFuncSetAttribute(gemm_mma, cudaFuncAttributeMaxDynamicSharedMemorySize, SMEMB);
    cudaFuncSetAttribute(lstm_persist, cudaFuncAttributeMaxDynamicSharedMemorySize, PS_SMEM);

    const int nW4 = 2*G4*Hsz/4;
    conv_kernel<<<(nW4+255)/256, 256>>>(Wih, Wih_c, nW4);
    conv_kernel<<<(nW4+255)/256, 256>>>(Whh, Whh_c, nW4);
    conv_kernel<<<(Vsz*Hsz/4+255)/256, 256>>>(decW, dW_c, Vsz*Hsz/4);
    embed_kernel<<<NBT, 128>>>(x, y, emb, yW, yb, inp);

    for (int l = 0; l < 2; l++) {
        const __half* Bmat = l ? seq : inp;
        // xgT[t][n][b] = Wih[n]·inp[t,b] + bih[n] + bhh[n]   (fp16 store)
        gemm_mma<<<dim3(G4/128, NBT/128), 256, SMEMB>>>(
            Wih_c + (size_t)l*G4*Hsz, Bmat,
            bih + l*G4, bhh + l*G4, nullptr, xgT, NBT, l ? 1 : 0, 1, 1);

        reset_bar<<<1, 4>>>();

        lstm_persist<<<dim3(Hsz/16, Bsz/128), 256, PS_SMEM>>>(
            xgT, Whh_c + (size_t)l*G4*Hsz, h0, h1, c, seq);
    }

    // decoder: out[(b*T+t)][v] = seq·decW^T + decb   (fp32 out)
    gemm_mma<<<dim3(Vsz/128, NBT/128), 256, SMEMB>>>(
        seq, dW_c, nullptr, nullptr, decb, out, Vsz, 0, 0, 0);
}

// round 10
// speedup vs baseline: 1.0418x; 1.0418x over previous
#include <cuda_runtime.h>
#include <cuda_fp16.h>
#include <stdint.h>
#include <math.h>

#define Bsz 512
#define Tsz 128
#define Hsz 512
#define Vsz 512
#define NBT 65536
#define G4  2048

// ---------------- device scratch ----------------
__device__ __align__(128) __half g_inp[(size_t)NBT*Hsz];
__device__ __align__(128) __half g_seq[(size_t)NBT*Hsz];
__device__ __align__(128) __half g_xgT[(size_t)Tsz*G4*Bsz];   // [t][n][b] fp16
__device__ __align__(128) __half g_h0[Bsz*Hsz], g_h1[Bsz*Hsz];
__device__ __align__(128) float  g_c[Bsz*Hsz];
__device__ __align__(128) __half g_Wih[2*(size_t)G4*Hsz];
__device__ __align__(128) __half g_Whh[2*(size_t)G4*Hsz];
__device__ __align__(128) __half g_dW[(size_t)Vsz*Hsz];
__device__ unsigned g_flag[4][8];   // [b-group][u-chunk], monotonic per layer

// ---------------- helpers ----------------
__device__ __forceinline__ uint32_t smem_u32(const void* p){
    uint32_t a; asm("{ .reg .u64 t; cvta.to.shared.u64 t, %1; cvt.u32.u64 %0, t; }" : "=r"(a) : "l"(p)); return a;
}
#define CP16(dst, src) asm volatile("cp.async.cg.shared.global [%0], [%1], 16;" :: "r"(dst), "l"(src))
#define CPCOMMIT()     asm volatile("cp.async.commit_group;" ::: "memory")
#define CPWAIT(n)      asm volatile("cp.async.wait_group %0;" :: "n"(n) : "memory")
#define LDSM4(r, a) asm volatile("ldmatrix.sync.aligned.m8n8.x4.shared.b16 {%0,%1,%2,%3}, [%4];" \
    : "=r"((r)[0]),"=r"((r)[1]),"=r"((r)[2]),"=r"((r)[3]) : "r"(a))

__device__ __forceinline__ void mma16816(float* d, const uint32_t* a, const uint32_t* b){
    asm volatile("mma.sync.aligned.m16n8k16.row.col.f32.f16.f16.f32 "
        "{%0,%1,%2,%3}, {%4,%5,%6,%7}, {%8,%9}, {%0,%1,%2,%3};"
        : "+f"(d[0]), "+f"(d[1]), "+f"(d[2]), "+f"(d[3])
        : "r"(a[0]), "r"(a[1]), "r"(a[2]), "r"(a[3]), "r"(b[0]), "r"(b[1]));
}

// ============ generic FF GEMM (fp16 operands, fp32 accum) ============
#define CHW 4608
#define STW 9216
#define SMEMB 110592   // 3 stages

__device__ __forceinline__ void load_chunk(uint32_t sbase,
    const __half* __restrict__ A, const __half* __restrict__ B,
    int m0, int n0, int ck, int bmap, int tid)
{
    #pragma unroll
    for (int i = tid; i < 1024; i += 256) {
        int r = i >> 3, q = i & 7;
        CP16(sbase + (r*36 + q*4)*4, A + (size_t)(m0 + r)*Hsz + ck*64 + q*8);
    }
    #pragma unroll
    for (int i = tid; i < 1024; i += 256) {
        int r = i >> 3, q = i & 7;
        int brow;
        if (bmap == 0)      brow = n0 + r;
        else                { int c = n0 + r; brow = (c & 511)*Tsz + (c >> 9); }
        CP16(sbase + (CHW + r*36 + q*4)*4, B + (size_t)brow*Hsz + ck*64 + q*8);
    }
    CPCOMMIT();
}

__device__ __forceinline__ void compute_chunk(uint32_t stg,
    float acc[4][4][4], int lane, int wm, int wn)
{
    int laneA_r = lane & 15;
    int laneA_c = (lane >> 4) * 4;
    int laneB_r = (lane & 7) + ((lane >> 4) << 3);
    int laneB_c = ((lane >> 3) & 1) * 4;
    #pragma unroll
    for (int ks = 0; ks < 4; ks++) {
        int kw = ks*8;
        uint32_t ah[4][4], bh[2][4];
        #pragma unroll
        for (int mt = 0; mt < 4; mt++) {
            uint32_t aw = (uint32_t)(wm*64 + mt*16 + laneA_r)*36 + kw + laneA_c;
            LDSM4(ah[mt], stg + aw*4);
        }
        #pragma unroll
        for (int np = 0; np < 2; np++) {
            uint32_t bw = (uint32_t)(wn*32 + np*16 + laneB_r)*36 + kw + laneB_c;
            LDSM4(bh[np], stg + (CHW + bw)*4);
        }
        #pragma unroll
        for (int mt = 0; mt < 4; mt++)
        #pragma unroll
        for (int nt = 0; nt < 4; nt++)
            mma16816(acc[mt][nt], ah[mt], &bh[nt>>1][(nt&1)*2]);
    }
}

__global__ void __launch_bounds__(256)
gemm_mma(const __half* __restrict__ A, const __half* __restrict__ B,
         const float* __restrict__ br1, const float* __restrict__ br2,
         const float* __restrict__ bcn, void* __restrict__ Cv,
         int Ntot, int bmap, int mx, int cmode)
{
    extern __shared__ uint32_t sm[];
    uint32_t sbase = smem_u32(sm);
    int tid = threadIdx.x, lane = tid & 31, wid = tid >> 5;
    int wm = wid >> 2, wn = wid & 3;
    int bm = mx ? blockIdx.x : blockIdx.y;
    int bn = mx ? blockIdx.y : blockIdx.x;
    int m0 = bm*128, n0 = bn*128;

    float acc[4][4][4];
    #pragma unroll
    for (int a = 0; a < 4; a++)
    #pragma unroll
    for (int b = 0; b < 4; b++)
    #pragma unroll
    for (int cc = 0; cc < 4; cc++) acc[a][b][cc] = 0.f;

    load_chunk(sbase, A, B, m0, n0, 0, bmap, tid);
    int st = 0, nst = 1;
    for (int k = 0; k < 8; k++) {
        if (k < 7) {
            load_chunk(sbase + nst*STW*4, A, B, m0, n0, k+1, bmap, tid);
            CPWAIT(1);
        } else {
            CPWAIT(0);
        }
        __syncthreads();
        compute_chunk(sbase + st*STW*4, acc, lane, wm, wn);
        st = nst; nst = (nst + 1 == 3) ? 0 : nst + 1;
    }

    #pragma unroll
    for (int mt = 0; mt < 4; mt++) {
        #pragma unroll
        for (int half = 0; half < 2; half++) {
            int m = m0 + wm*64 + mt*16 + (lane >> 2) + half*8;
            float rb = br1 ? (br1[m] + br2[m]) : 0.f;
            #pragma unroll
            for (int nt = 0; nt < 4; nt++) {
                int c = n0 + wn*32 + nt*8 + (lane & 3)*2;
                float v0 = acc[mt][nt][half*2+0] + rb;
                float v1 = acc[mt][nt][half*2+1] + rb;
                if (bcn) { v0 += bcn[c]; v1 += bcn[c+1]; }
                if (cmode) {
                    __half* dst = (__half*)Cv + ((size_t)(c >> 9)*G4 + m)*Bsz + (c & 511);
                    __half2 hv; hv.x = __float2half_rn(v0); hv.y = __float2half_rn(v1);
                    *(__half2*)dst = hv;
                } else {
                    *(float2*)((float*)Cv + (size_t)m*Ntot + c) = make_float2(v0, v1);
                }
            }
        }
    }
}

// ============ persistent LSTM recurrence (fp16, chunk-flag sync) ============
// grid (32,4): x -> 16 units (u0), y -> 128 batch (b0).
// Per-chunk producer flags replace the per-step group barrier.
// SMEM: W 8ck x 64r x 36w (73728B); H 3st x 128r x 36w (55296B)
#define PS_SMEM 129536
__device__ __forceinline__ int WOFFf(int ck,int r){ return (ck*64 + r)*36; }
__device__ __forceinline__ int HOFFf(int st,int r){ return 18432 + (st*128 + r)*36; }

__global__ void reset_flags(){ int i = threadIdx.x; if (i < 32) ((unsigned*)g_flag)[i] = 0u; }

__global__ void __launch_bounds__(256,1)
lstm_persist(const __half* __restrict__ xg, const __half* __restrict__ W,
             __half* __restrict__ h0, __half* __restrict__ h1,
             float* __restrict__ cst, __half* __restrict__ seq)
{
    extern __shared__ uint32_t sm[];
    uint32_t sb = smem_u32(sm);
    int tid = threadIdx.x, lane = tid & 31, w = tid >> 5;
    int laneR = lane >> 2, laneC = lane & 3;
    int u0 = blockIdx.x * 16;
    int b0 = blockIdx.y * 128;
    int gid = blockIdx.y;
    int myck = u0 >> 6;                    // chunk this CTA's h slice belongs to

    int laneA_r = lane & 15;
    int laneA_c = (lane >> 4) * 4;
    int laneB_r = (lane & 7) + ((lane >> 4) << 3);
    int laneB_c = ((lane >> 3) & 1) * 4;

    // ---- persistent W tile: rows n = g*16+ul -> Whh row g*512 + u0+ul ----
    for (int i = tid; i < 4096; i += 256) {
        int ck = i >> 9, rem = i & 511;
        int r = rem >> 3, q = rem & 7;
        int g = r >> 4, ul = r & 15;
        CP16(sb + (WOFFf(ck,r) + q*4)*4,
             W + ((size_t)(g*Hsz + u0 + ul))*Hsz + ck*64 + q*8);
    }
    CPCOMMIT(); CPWAIT(0);
    __syncthreads();

    __half* hb[2] = {h0, h1};

    for (int t = 0; t < Tsz; t++) {
        const __half* Hc = hb[t & 1];
        __half* Nx = hb[(t+1) & 1];
        unsigned tgt = 4u * (unsigned)t;   // flag threshold for h(t) availability

        // xg prefetch (independent of h)
        float xv[2][16];
        {
            const __half* xgt = xg + (size_t)t*G4*Bsz;
            #pragma unroll
            for (int half = 0; half < 2; half++) {
                int b = b0 + w*16 + laneR + half*8;
                #pragma unroll
                for (int uh = 0; uh < 2; uh++)
                #pragma unroll
                for (int du = 0; du < 2; du++) {
                    int u = u0 + laneC*2 + uh*8 + du;
                    #pragma unroll
                    for (int g = 0; g < 4; g++)
                        xv[half][uh*8 + du*4 + g] =
                            __half2float(xgt[((size_t)(g*Hsz + u))*Bsz + b]);
                }
            }
        }

        float acc[8][4];
        #pragma unroll
        for (int i = 0; i < 8; i++)
        #pragma unroll
        for (int j = 0; j < 4; j++) acc[i][j] = 0.f;

        if (t > 0) {
            // wait for chunk availability (all threads spin; converged per warp)
            auto wait_ck = [&](int ck){
                unsigned v;
                do { asm volatile("ld.acquire.gpu.global.u32 %0, [%1];"
                                  : "=r"(v) : "l"(&g_flag[gid][ck])); } while (v < tgt);
            };
            auto ldh = [&](int ck, int st){
                #pragma unroll
                for (int i = tid; i < 1024; i += 256) {
                    int r = i >> 3, q = i & 7;
                    CP16(sb + (HOFFf(st,r) + q*4)*4,
                         Hc + (size_t)(b0 + r)*Hsz + ck*64 + q*8);
                }
                CPCOMMIT();
            };

            wait_ck(0);
            ldh(0, 0);
            int st = 0, nst = 1;
            for (int ck = 0; ck < 8; ck++) {
                if (ck < 7) { wait_ck(ck+1); ldh(ck+1, nst); CPWAIT(1); }
                else        { CPWAIT(0); }
                __syncthreads();
                #pragma unroll
                for (int ks = 0; ks < 4; ks++) {
                    int kw = ks*8;
                    uint32_t ah[4], bh[4][4];
                    uint32_t aw = (uint32_t)(HOFFf(st, w*16 + laneA_r)) + kw + laneA_c;
                    LDSM4(ah, sb + aw*4);
                    #pragma unroll
                    for (int np = 0; np < 4; np++) {
                        uint32_t bw = (uint32_t)(WOFFf(ck, np*16 + laneB_r)) + kw + laneB_c;
                        LDSM4(bh[np], sb + bw*4);
                    }
                    #pragma unroll
                    for (int nt = 0; nt < 8; nt++)
                        mma16816(acc[nt], ah, &bh[nt>>1][(nt&1)*2]);
                }
                st = nst; nst = (nst + 1 == 3) ? 0 : nst + 1;
            }
        }

        // epilogue: gates + state update (c=0 at t=0)
        #pragma unroll
        for (int half = 0; half < 2; half++) {
            int b = b0 + w*16 + laneR + half*8;
            #pragma unroll
            for (int uh = 0; uh < 2; uh++) {
                float cn[2], hn[2];
                #pragma unroll
                for (int du = 0; du < 2; du++) {
                    int q = half*2 + du;
                    float gi = acc[0*2+uh][q] + xv[half][uh*8+du*4+0];
                    float gf = acc[1*2+uh][q] + xv[half][uh*8+du*4+1];
                    float gg = acc[2*2+uh][q] + xv[half][uh*8+du*4+2];
                    float go = acc[3*2+uh][q] + xv[half][uh*8+du*4+3];
                    float is = 1.f/(1.f + __expf(-gi));
                    float fs = 1.f/(1.f + __expf(-gf));
                    float os = 1.f/(1.f + __expf(-go));
                    float gt = tanhf(gg);
                    int u = u0 + laneC*2 + uh*8 + du;
                    float co = (t > 0) ? cst[(size_t)b*Hsz + u] : 0.f;
                    cn[du] = fs*co + is*gt;
                    hn[du] = os*tanhf(cn[du]);
                }
                int u2 = u0 + laneC*2 + uh*8;
                size_t so = (size_t)b*Hsz + u2;
                *(float2*)(cst + so) = make_float2(cn[0], cn[1]);
                __half2 hp;
                hp.x = __float2half_rn(hn[0]);
                hp.y = __float2half_rn(hn[1]);
                *(__half2*)(Nx + so) = hp;
                *(__half2*)(seq + ((size_t)b*Tsz + t)*Hsz + u2) = hp;
            }
        }

        // publish this CTA's h(t+1) slice (chunk-granular, monotonic)
        if (t < Tsz - 1) {
            __threadfence();
            __syncthreads();
            if (tid == 0) atomicAdd(&g_flag[gid][myck], 1u);
        }
    }
}

// ---------------- small kernels ----------------
__global__ void conv_kernel(const float* __restrict__ s, __half* __restrict__ h, int n4){
    int i = blockIdx.x*blockDim.x + threadIdx.x;
    if (i < n4) {
        float4 v = ((const float4*)s)[i];
        __half2 a, b;
        a.x = __float2half_rn(v.x); a.y = __float2half_rn(v.y);
        b.x = __float2half_rn(v.z); b.y = __float2half_rn(v.w);
        ((__half2*)h)[i*2]   = a;
        ((__half2*)h)[i*2+1] = b;
    }
}
__global__ void embed_kernel(const int* __restrict__ x, const float* __restrict__ y,
                             const float* __restrict__ emb, const float* __restrict__ yW,
                             const float* __restrict__ yb, __half* __restrict__ o){
    int bt = blockIdx.x;            // bt = t*512 + b
    int t = bt >> 9, b = bt & 511;
    int h4 = threadIdx.x;           // 128 threads x 4 elems
    int tok = (t == 0) ? Vsz : x[b*Tsz + t - 1];
    float4 e = ((const float4*)(emb + (size_t)tok*Hsz))[h4];
    float4 wv = ((const float4*)yW)[h4];
    float4 bv = ((const float4*)yb)[h4];
    float yy = y[b];
    __half2 a, c;
    a.x = __float2half_rn(e.x + yy*wv.x + bv.x);
    a.y = __float2half_rn(e.y + yy*wv.y + bv.y);
    c.x = __float2half_rn(e.z + yy*wv.z + bv.z);
    c.y = __float2half_rn(e.w + yy*wv.w + bv.w);
    ((__half2*)(o + (size_t)bt*Hsz))[h4*2]   = a;
    ((__half2*)(o + (size_t)bt*Hsz))[h4*2+1] = c;
}

// ---------------- launch ----------------
extern "C" void kernel_launch(void* const* d_in, const int* in_sizes, int n_in,
                              void* d_out, int out_size)
{
    const int*   x    = (const int*)  d_in[0];
    const float* y    = (const float*)d_in[1];
    const float* emb  = (const float*)d_in[2];
    const float* yW   = (const float*)d_in[3];
    const float* yb   = (const float*)d_in[4];
    const float* Wih  = (const float*)d_in[5];
    const float* Whh  = (const float*)d_in[6];
    const float* bih  = (const float*)d_in[7];
    const float* bhh  = (const float*)d_in[8];
    const float* decW = (const float*)d_in[9];
    const float* decb = (const float*)d_in[10];
    float* out = (float*)d_out;

    __half *inp, *seq, *Wih_c, *Whh_c, *dW_c, *h0, *h1, *xgT;
    float *c;
    cudaGetSymbolAddress((void**)&inp,   g_inp);
    cudaGetSymbolAddress((void**)&seq,   g_seq);
    cudaGetSymbolAddress((void**)&xgT,   g_xgT);
    cudaGetSymbolAddress((void**)&h0,    g_h0);
    cudaGetSymbolAddress((void**)&h1,    g_h1);
    cudaGetSymbolAddress((void**)&c,     g_c);
    cudaGetSymbolAddress((void**)&Wih_c, g_Wih);
    cudaGetSymbolAddress((void**)&Whh_c, g_Whh);
    cudaGetSymbolAddress((void**)&dW_c,  g_dW);

    cudaFuncSetAttribute(gemm_mma, cudaFuncAttributeMaxDynamicSharedMemorySize, SMEMB);
    cudaFuncSetAttribute(lstm_persist, cudaFuncAttributeMaxDynamicSharedMemorySize, PS_SMEM);

    const int nW4 = 2*G4*Hsz/4;
    conv_kernel<<<(nW4+255)/256, 256>>>(Wih, Wih_c, nW4);
    conv_kernel<<<(nW4+255)/256, 256>>>(Whh, Whh_c, nW4);
    conv_kernel<<<(Vsz*Hsz/4+255)/256, 256>>>(decW, dW_c, Vsz*Hsz/4);
    embed_kernel<<<NBT, 128>>>(x, y, emb, yW, yb, inp);

    for (int l = 0; l < 2; l++) {
        const __half* Bmat = l ? seq : inp;
        // xgT[t][n][b] = Wih[n]·inp[t,b] + bih[n] + bhh[n]   (fp16 store)
        gemm_mma<<<dim3(G4/128, NBT/128), 256, SMEMB>>>(
            Wih_c + (size_t)l*G4*Hsz, Bmat,
            bih + l*G4, bhh + l*G4, nullptr, xgT, NBT, l ? 1 : 0, 1, 1);

        reset_flags<<<1, 32>>>();

        lstm_persist<<<dim3(Hsz/16, Bsz/128), 256, PS_SMEM>>>(
            xgT, Whh_c + (size_t)l*G4*Hsz, h0, h1, c, seq);
    }

    // decoder: out[(b*T+t)][v] = seq·decW^T + decb   (fp32 out)
    gemm_mma<<<dim3(Vsz/128, NBT/128), 256, SMEMB>>>(
        seq, dW_c, nullptr, nullptr, decb, out, Vsz, 0, 0, 0);
}

// round 11
// speedup vs baseline: 1.0926x; 1.0487x over previous
#include <cuda_runtime.h>
#include <cuda_fp16.h>
#include <stdint.h>
#include <math.h>

#define Bsz 512
#define Tsz 128
#define Hsz 512
#define Vsz 512
#define NBT 65536
#define G4  2048

// ---------------- device scratch ----------------
__device__ __align__(128) __half g_inp[(size_t)NBT*Hsz];
__device__ __align__(128) __half g_seq[(size_t)NBT*Hsz];
__device__ __align__(128) __half g_xgT[(size_t)Tsz*G4*Bsz];   // [t][u][b][g] fp16
__device__ __align__(128) __half g_h0[Bsz*Hsz], g_h1[Bsz*Hsz];
__device__ __align__(128) float  g_c[Bsz*Hsz];                 // unused (c in regs)
__device__ __align__(128) __half g_Wih[2*(size_t)G4*Hsz];
__device__ __align__(128) __half g_Whh[2*(size_t)G4*Hsz];
__device__ __align__(128) __half g_dW[(size_t)Vsz*Hsz];
__device__ unsigned g_flag[4][8];   // [b-group][u-chunk], monotonic per layer

// ---------------- helpers ----------------
__device__ __forceinline__ uint32_t smem_u32(const void* p){
    uint32_t a; asm("{ .reg .u64 t; cvta.to.shared.u64 t, %1; cvt.u32.u64 %0, t; }" : "=r"(a) : "l"(p)); return a;
}
#define CP16(dst, src) asm volatile("cp.async.cg.shared.global [%0], [%1], 16;" :: "r"(dst), "l"(src))
#define CPCOMMIT()     asm volatile("cp.async.commit_group;" ::: "memory")
#define CPWAIT(n)      asm volatile("cp.async.wait_group %0;" :: "n"(n) : "memory")
#define LDSM4(r, a) asm volatile("ldmatrix.sync.aligned.m8n8.x4.shared.b16 {%0,%1,%2,%3}, [%4];" \
    : "=r"((r)[0]),"=r"((r)[1]),"=r"((r)[2]),"=r"((r)[3]) : "r"(a))

__device__ __forceinline__ void mma16816(float* d, const uint32_t* a, const uint32_t* b){
    asm volatile("mma.sync.aligned.m16n8k16.row.col.f32.f16.f16.f32 "
        "{%0,%1,%2,%3}, {%4,%5,%6,%7}, {%8,%9}, {%0,%1,%2,%3};"
        : "+f"(d[0]), "+f"(d[1]), "+f"(d[2]), "+f"(d[3])
        : "r"(a[0]), "r"(a[1]), "r"(a[2]), "r"(a[3]), "r"(b[0]), "r"(b[1]));
}

// ============ generic FF GEMM (fp16 operands, fp32 accum) ============
#define CHW 4608
#define STW 9216
#define SMEMB 110592   // 3 stages

// amap: A tile row r -> weight row (r>>5)*512 + m0 + (r&31)  (4 gates x 32 units)
__device__ __forceinline__ void load_chunk(uint32_t sbase,
    const __half* __restrict__ A, const __half* __restrict__ B,
    int m0, int n0, int ck, int bmap, int amap, int tid)
{
    #pragma unroll
    for (int i = tid; i < 1024; i += 256) {
        int r = i >> 3, q = i & 7;
        int arow = amap ? (((r >> 5) << 9) + m0 + (r & 31)) : (m0 + r);
        CP16(sbase + (r*36 + q*4)*4, A + (size_t)arow*Hsz + ck*64 + q*8);
    }
    #pragma unroll
    for (int i = tid; i < 1024; i += 256) {
        int r = i >> 3, q = i & 7;
        int brow;
        if (bmap == 0)      brow = n0 + r;
        else                { int c = n0 + r; brow = (c & 511)*Tsz + (c >> 9); }
        CP16(sbase + (CHW + r*36 + q*4)*4, B + (size_t)brow*Hsz + ck*64 + q*8);
    }
    CPCOMMIT();
}

__device__ __forceinline__ void compute_chunk(uint32_t stg,
    float acc[4][4][4], int lane, int wm, int wn)
{
    int laneA_r = lane & 15;
    int laneA_c = (lane >> 4) * 4;
    int laneB_r = (lane & 7) + ((lane >> 4) << 3);
    int laneB_c = ((lane >> 3) & 1) * 4;
    #pragma unroll
    for (int ks = 0; ks < 4; ks++) {
        int kw = ks*8;
        uint32_t ah[4][4], bh[2][4];
        #pragma unroll
        for (int mt = 0; mt < 4; mt++) {
            uint32_t aw = (uint32_t)(wm*64 + mt*16 + laneA_r)*36 + kw + laneA_c;
            LDSM4(ah[mt], stg + aw*4);
        }
        #pragma unroll
        for (int np = 0; np < 2; np++) {
            uint32_t bw = (uint32_t)(wn*32 + np*16 + laneB_r)*36 + kw + laneB_c;
            LDSM4(bh[np], stg + (CHW + bw)*4);
        }
        #pragma unroll
        for (int mt = 0; mt < 4; mt++)
        #pragma unroll
        for (int nt = 0; nt < 4; nt++)
            mma16816(acc[mt][nt], ah[mt], &bh[nt>>1][(nt&1)*2]);
    }
}

__global__ void __launch_bounds__(256)
gemm_mma(const __half* __restrict__ A, const __half* __restrict__ B,
         const float* __restrict__ br1, const float* __restrict__ br2,
         const float* __restrict__ bcn, void* __restrict__ Cv,
         int Ntot, int bmap, int mx, int cmode)
{
    extern __shared__ uint32_t sm[];
    uint32_t sbase = smem_u32(sm);
    int tid = threadIdx.x, lane = tid & 31, wid = tid >> 5;
    int wm = wid >> 2, wn = wid & 3;
    int bm = mx ? blockIdx.x : blockIdx.y;
    int bn = mx ? blockIdx.y : blockIdx.x;
    int m0 = cmode ? bm*32 : bm*128;    // cmode: u0 (gate-mapped rows)
    int n0 = bn*128;

    float acc[4][4][4];
    #pragma unroll
    for (int a = 0; a < 4; a++)
    #pragma unroll
    for (int b = 0; b < 4; b++)
    #pragma unroll
    for (int cc = 0; cc < 4; cc++) acc[a][b][cc] = 0.f;

    load_chunk(sbase, A, B, m0, n0, 0, bmap, cmode, tid);
    int st = 0, nst = 1;
    for (int k = 0; k < 8; k++) {
        if (k < 7) {
            load_chunk(sbase + nst*STW*4, A, B, m0, n0, k+1, bmap, cmode, tid);
            CPWAIT(1);
        } else {
            CPWAIT(0);
        }
        __syncthreads();
        compute_chunk(sbase + st*STW*4, acc, lane, wm, wn);
        st = nst; nst = (nst + 1 == 3) ? 0 : nst + 1;
    }

    if (cmode) {
        // ---- transpose epilogue: SMEM [ul(32)][cloc(128,pad132)][g(4)] halves ----
        __syncthreads();                         // stages no longer needed
        __half* sx = (__half*)sm;
        #pragma unroll
        for (int mt = 0; mt < 4; mt++) {
            #pragma unroll
            for (int half = 0; half < 2; half++) {
                int rloc = wm*64 + mt*16 + (lane >> 2) + half*8;
                int g = rloc >> 5, ul = rloc & 31;
                int nrow = (g << 9) + m0 + ul;
                float rb = br1[nrow] + br2[nrow];
                #pragma unroll
                for (int nt = 0; nt < 4; nt++) {
                    int cloc = wn*32 + nt*8 + (lane & 3)*2;
                    sx[(ul*132 + cloc)*4 + g]     = __float2half_rn(acc[mt][nt][half*2+0] + rb);
                    sx[(ul*132 + cloc + 1)*4 + g] = __float2half_rn(acc[mt][nt][half*2+1] + rb);
                }
            }
        }
        __syncthreads();
        int t = n0 >> 9, bwin = n0 & 511;
        #pragma unroll
        for (int i = tid; i < 4096; i += 256) {
            int ul = i >> 7, bl = i & 127;
            uint2 v = *(uint2*)&sx[(ul*132 + bl)*4];
            *(uint2*)((__half*)Cv + (((size_t)t*512 + m0 + ul)*512 + bwin + bl)*4) = v;
        }
        return;
    }

    #pragma unroll
    for (int mt = 0; mt < 4; mt++) {
        #pragma unroll
        for (int half = 0; half < 2; half++) {
            int m = m0 + wm*64 + mt*16 + (lane >> 2) + half*8;
            float rb = br1 ? (br1[m] + br2[m]) : 0.f;
            #pragma unroll
            for (int nt = 0; nt < 4; nt++) {
                int c = n0 + wn*32 + nt*8 + (lane & 3)*2;
                float v0 = acc[mt][nt][half*2+0] + rb;
                float v1 = acc[mt][nt][half*2+1] + rb;
                if (bcn) { v0 += bcn[c]; v1 += bcn[c+1]; }
                *(float2*)((float*)Cv + (size_t)m*Ntot + c) = make_float2(v0, v1);
            }
        }
    }
}

// ============ persistent LSTM recurrence (fp16, chunk-flag sync, c in regs) ============
#define PS_SMEM 129536
__device__ __forceinline__ int WOFFf(int ck,int r){ return (ck*64 + r)*36; }
__device__ __forceinline__ int HOFFf(int st,int r){ return 18432 + (st*128 + r)*36; }

__global__ void reset_flags(){ int i = threadIdx.x; if (i < 32) ((unsigned*)g_flag)[i] = 0u; }

__global__ void __launch_bounds__(256,1)
lstm_persist(const __half* __restrict__ xg, const __half* __restrict__ W,
             __half* __restrict__ h0, __half* __restrict__ h1,
             __half* __restrict__ seq)
{
    extern __shared__ uint32_t sm[];
    uint32_t sb = smem_u32(sm);
    int tid = threadIdx.x, lane = tid & 31, w = tid >> 5;
    int laneR = lane >> 2, laneC = lane & 3;
    int u0 = blockIdx.x * 16;
    int b0 = blockIdx.y * 128;
    int gid = blockIdx.y;
    int myck = u0 >> 6;

    int laneA_r = lane & 15;
    int laneA_c = (lane >> 4) * 4;
    int laneB_r = (lane & 7) + ((lane >> 4) << 3);
    int laneB_c = ((lane >> 3) & 1) * 4;

    // ---- persistent W tile ----
    for (int i = tid; i < 4096; i += 256) {
        int ck = i >> 9, rem = i & 511;
        int r = rem >> 3, q = rem & 7;
        int g = r >> 4, ul = r & 15;
        CP16(sb + (WOFFf(ck,r) + q*4)*4,
             W + ((size_t)(g*Hsz + u0 + ul))*Hsz + ck*64 + q*8);
    }
    CPCOMMIT(); CPWAIT(0);
    __syncthreads();

    __half* hb[2] = {h0, h1};
    float creg[2][2][2];                // [half][uh][du] — persistent c state
    #pragma unroll
    for (int a = 0; a < 2; a++)
    #pragma unroll
    for (int b = 0; b < 2; b++) { creg[a][b][0] = 0.f; creg[a][b][1] = 0.f; }

    for (int t = 0; t < Tsz; t++) {
        const __half* Hc = hb[t & 1];
        __half* Nx = hb[(t+1) & 1];
        unsigned tgt = 4u * (unsigned)t;

        // xg prefetch: 8B gate vectors, quad-coalesced
        float xv[2][16];
        {
            const __half* xgt = xg + (size_t)t*G4*Bsz;
            #pragma unroll
            for (int half = 0; half < 2; half++) {
                int b = b0 + w*16 + laneR + half*8;
                #pragma unroll
                for (int uh = 0; uh < 2; uh++)
                #pragma unroll
                for (int du = 0; du < 2; du++) {
                    int u = u0 + laneC*2 + uh*8 + du;
                    uint2 v = *(const uint2*)(xgt + ((size_t)u*512 + b)*4);
                    __half2 p0 = *(__half2*)&v.x;
                    __half2 p1 = *(__half2*)&v.y;
                    xv[half][uh*8+du*4+0] = __half2float(p0.x);
                    xv[half][uh*8+du*4+1] = __half2float(p0.y);
                    xv[half][uh*8+du*4+2] = __half2float(p1.x);
                    xv[half][uh*8+du*4+3] = __half2float(p1.y);
                }
            }
        }

        float acc[8][4];
        #pragma unroll
        for (int i = 0; i < 8; i++)
        #pragma unroll
        for (int j = 0; j < 4; j++) acc[i][j] = 0.f;

        if (t > 0) {
            auto wait_ck = [&](int ck){
                unsigned v;
                do { asm volatile("ld.acquire.gpu.global.u32 %0, [%1];"
                                  : "=r"(v) : "l"(&g_flag[gid][ck])); } while (v < tgt);
            };
            auto ldh = [&](int ck, int st){
                #pragma unroll
                for (int i = tid; i < 1024; i += 256) {
                    int r = i >> 3, q = i & 7;
                    CP16(sb + (HOFFf(st,r) + q*4)*4,
                         Hc + (size_t)(b0 + r)*Hsz + ck*64 + q*8);
                }
                CPCOMMIT();
            };

            wait_ck(0);
            ldh(0, 0);
            int st = 0, nst = 1;
            for (int ck = 0; ck < 8; ck++) {
                if (ck < 7) { wait_ck(ck+1); ldh(ck+1, nst); CPWAIT(1); }
                else        { CPWAIT(0); }
                __syncthreads();
                #pragma unroll
                for (int ks = 0; ks < 4; ks++) {
                    int kw = ks*8;
                    uint32_t ah[4], bh[4][4];
                    uint32_t aw = (uint32_t)(HOFFf(st, w*16 + laneA_r)) + kw + laneA_c;
                    LDSM4(ah, sb + aw*4);
                    #pragma unroll
                    for (int np = 0; np < 4; np++) {
                        uint32_t bw = (uint32_t)(WOFFf(ck, np*16 + laneB_r)) + kw + laneB_c;
                        LDSM4(bh[np], sb + bw*4);
                    }
                    #pragma unroll
                    for (int nt = 0; nt < 8; nt++)
                        mma16816(acc[nt], ah, &bh[nt>>1][(nt&1)*2]);
                }
                st = nst; nst = (nst + 1 == 3) ? 0 : nst + 1;
            }
        }

        // epilogue: gates + state update (c in registers)
        #pragma unroll
        for (int half = 0; half < 2; half++) {
            int b = b0 + w*16 + laneR + half*8;
            #pragma unroll
            for (int uh = 0; uh < 2; uh++) {
                float hn[2];
                #pragma unroll
                for (int du = 0; du < 2; du++) {
                    int q = half*2 + du;
                    float gi = acc[0*2+uh][q] + xv[half][uh*8+du*4+0];
                    float gf = acc[1*2+uh][q] + xv[half][uh*8+du*4+1];
                    float gg = acc[2*2+uh][q] + xv[half][uh*8+du*4+2];
                    float go = acc[3*2+uh][q] + xv[half][uh*8+du*4+3];
                    float is = 1.f/(1.f + __expf(-gi));
                    float fs = 1.f/(1.f + __expf(-gf));
                    float os = 1.f/(1.f + __expf(-go));
                    float gt = tanhf(gg);
                    float cn = fs*creg[half][uh][du] + is*gt;
                    creg[half][uh][du] = cn;
                    hn[du] = os*tanhf(cn);
                }
                int u2 = u0 + laneC*2 + uh*8;
                __half2 hp;
                hp.x = __float2half_rn(hn[0]);
                hp.y = __float2half_rn(hn[1]);
                *(__half2*)(Nx + (size_t)b*Hsz + u2) = hp;
                *(__half2*)(seq + ((size_t)b*Tsz + t)*Hsz + u2) = hp;
            }
        }

        if (t < Tsz - 1) {
            __threadfence();
            __syncthreads();
            if (tid == 0) atomicAdd(&g_flag[gid][myck], 1u);
        }
    }
}

// ---------------- small kernels ----------------
__global__ void conv_kernel(const float* __restrict__ s, __half* __restrict__ h, int n4){
    int i = blockIdx.x*blockDim.x + threadIdx.x;
    if (i < n4) {
        float4 v = ((const float4*)s)[i];
        __half2 a, b;
        a.x = __float2half_rn(v.x); a.y = __float2half_rn(v.y);
        b.x = __float2half_rn(v.z); b.y = __float2half_rn(v.w);
        ((__half2*)h)[i*2]   = a;
        ((__half2*)h)[i*2+1] = b;
    }
}
__global__ void embed_kernel(const int* __restrict__ x, const float* __restrict__ y,
                             const float* __restrict__ emb, const float* __restrict__ yW,
                             const float* __restrict__ yb, __half* __restrict__ o){
    int bt = blockIdx.x;            // bt = t*512 + b
    int t = bt >> 9, b = bt & 511;
    int h4 = threadIdx.x;
    int tok = (t == 0) ? Vsz : x[b*Tsz + t - 1];
    float4 e = ((const float4*)(emb + (size_t)tok*Hsz))[h4];
    float4 wv = ((const float4*)yW)[h4];
    float4 bv = ((const float4*)yb)[h4];
    float yy = y[b];
    __half2 a, c;
    a.x = __float2half_rn(e.x + yy*wv.x + bv.x);
    a.y = __float2half_rn(e.y + yy*wv.y + bv.y);
    c.x = __float2half_rn(e.z + yy*wv.z + bv.z);
    c.y = __float2half_rn(e.w + yy*wv.w + bv.w);
    ((__half2*)(o + (size_t)bt*Hsz))[h4*2]   = a;
    ((__half2*)(o + (size_t)bt*Hsz))[h4*2+1] = c;
}

// ---------------- launch ----------------
extern "C" void kernel_launch(void* const* d_in, const int* in_sizes, int n_in,
                              void* d_out, int out_size)
{
    const int*   x    = (const int*)  d_in[0];
    const float* y    = (const float*)d_in[1];
    const float* emb  = (const float*)d_in[2];
    const float* yW   = (const float*)d_in[3];
    const float* yb   = (const float*)d_in[4];
    const float* Wih  = (const float*)d_in[5];
    const float* Whh  = (const float*)d_in[6];
    const float* bih  = (const float*)d_in[7];
    const float* bhh  = (const float*)d_in[8];
    const float* decW = (const float*)d_in[9];
    const float* decb = (const float*)d_in[10];
    float* out = (float*)d_out;

    __half *inp, *seq, *Wih_c, *Whh_c, *dW_c, *h0, *h1, *xgT;
    cudaGetSymbolAddress((void**)&inp,   g_inp);
    cudaGetSymbolAddress((void**)&seq,   g_seq);
    cudaGetSymbolAddress((void**)&xgT,   g_xgT);
    cudaGetSymbolAddress((void**)&h0,    g_h0);
    cudaGetSymbolAddress((void**)&h1,    g_h1);
    cudaGetSymbolAddress((void**)&Wih_c, g_Wih);
    cudaGetSymbolAddress((void**)&Whh_c, g_Whh);
    cudaGetSymbolAddress((void**)&dW_c,  g_dW);

    cudaFuncSetAttribute(gemm_mma, cudaFuncAttributeMaxDynamicSharedMemorySize, SMEMB);
    cudaFuncSetAttribute(lstm_persist, cudaFuncAttributeMaxDynamicSharedMemorySize, PS_SMEM);

    const int nW4 = 2*G4*Hsz/4;
    conv_kernel<<<(nW4+255)/256, 256>>>(Wih, Wih_c, nW4);
    conv_kernel<<<(nW4+255)/256, 256>>>(Whh, Whh_c, nW4);
    conv_kernel<<<(Vsz*Hsz/4+255)/256, 256>>>(decW, dW_c, Vsz*Hsz/4);
    embed_kernel<<<NBT, 128>>>(x, y, emb, yW, yb, inp);

    for (int l = 0; l < 2; l++) {
        const __half* Bmat = l ? seq : inp;
        // xgT[t][u][b][g] = Wih[g*512+u]·inp[t,b] + bih + bhh   (fp16, gate-vector layout)
        gemm_mma<<<dim3(G4/128, NBT/128), 256, SMEMB>>>(
            Wih_c + (size_t)l*G4*Hsz, Bmat,
            bih + l*G4, bhh + l*G4, nullptr, xgT, NBT, l ? 1 : 0, 1, 1);

        reset_flags<<<1, 32>>>();

        lstm_persist<<<dim3(Hsz/16, Bsz/128), 256, PS_SMEM>>>(
            xgT, Whh_c + (size_t)l*G4*Hsz, h0, h1, seq);
    }

    // decoder: out[(b*T+t)][v] = seq·decW^T + decb   (fp32 out)
    gemm_mma<<<dim3(Vsz/128, NBT/128), 256, SMEMB>>>(
        seq, dW_c, nullptr, nullptr, decb, out, Vsz, 0, 0, 0);
}

// round 12
// speedup vs baseline: 1.2710x; 1.1633x over previous
#include <cuda_runtime.h>
#include <cuda_fp16.h>
#include <stdint.h>
#include <math.h>

#define Bsz 512
#define Tsz 128
#define Hsz 512
#define Vsz 512
#define NBT 65536
#define G4  2048
#define TOKP 640   // padded token count (513 -> 640)

// ---------------- device scratch ----------------
__device__ __align__(128) __half g_seq[(size_t)NBT*Hsz];
__device__ __align__(128) __half g_xgT[(size_t)Tsz*G4*Bsz];   // [t][u][b][g] fp16 (layer 1 only)
__device__ __align__(128) __half g_h0[Bsz*Hsz], g_h1[Bsz*Hsz];
__device__ __align__(128) __half g_Wih[2*(size_t)G4*Hsz];
__device__ __align__(128) __half g_Whh[2*(size_t)G4*Hsz];
__device__ __align__(128) __half g_dW[(size_t)Vsz*Hsz];
__device__ __align__(128) __half g_embp[TOKP*Hsz];            // padded fp16 emb
__device__ __align__(128) __half g_Ep[(size_t)TOKP*Hsz*4];    // E' [tok][u][g] fp16
__device__ __align__(128) float  g_wyv[G4], g_cbv[G4];        // [u*4+g] fp32
__device__ unsigned g_flag[4][8];

// ---------------- helpers ----------------
__device__ __forceinline__ uint32_t smem_u32(const void* p){
    uint32_t a; asm("{ .reg .u64 t; cvta.to.shared.u64 t, %1; cvt.u32.u64 %0, t; }" : "=r"(a) : "l"(p)); return a;
}
#define CP16(dst, src) asm volatile("cp.async.cg.shared.global [%0], [%1], 16;" :: "r"(dst), "l"(src))
#define CPCOMMIT()     asm volatile("cp.async.commit_group;" ::: "memory")
#define CPWAIT(n)      asm volatile("cp.async.wait_group %0;" :: "n"(n) : "memory")
#define LDSM4(r, a) asm volatile("ldmatrix.sync.aligned.m8n8.x4.shared.b16 {%0,%1,%2,%3}, [%4];" \
    : "=r"((r)[0]),"=r"((r)[1]),"=r"((r)[2]),"=r"((r)[3]) : "r"(a))

__device__ __forceinline__ void mma16816(float* d, const uint32_t* a, const uint32_t* b){
    asm volatile("mma.sync.aligned.m16n8k16.row.col.f32.f16.f16.f32 "
        "{%0,%1,%2,%3}, {%4,%5,%6,%7}, {%8,%9}, {%0,%1,%2,%3};"
        : "+f"(d[0]), "+f"(d[1]), "+f"(d[2]), "+f"(d[3])
        : "r"(a[0]), "r"(a[1]), "r"(a[2]), "r"(a[3]), "r"(b[0]), "r"(b[1]));
}

// ============ generic FF GEMM (fp16 operands, fp32 accum) ============
#define CHW 4608
#define STW 9216
#define SMEMB 110592   // 3 stages

__device__ __forceinline__ void load_chunk(uint32_t sbase,
    const __half* __restrict__ A, const __half* __restrict__ B,
    int m0, int n0, int ck, int bmap, int amap, int tid)
{
    #pragma unroll
    for (int i = tid; i < 1024; i += 256) {
        int r = i >> 3, q = i & 7;
        int arow = amap ? (((r >> 5) << 9) + m0 + (r & 31)) : (m0 + r);
        CP16(sbase + (r*36 + q*4)*4, A + (size_t)arow*Hsz + ck*64 + q*8);
    }
    #pragma unroll
    for (int i = tid; i < 1024; i += 256) {
        int r = i >> 3, q = i & 7;
        int brow;
        if (bmap == 0)      brow = n0 + r;
        else                { int c = n0 + r; brow = (c & 511)*Tsz + (c >> 9); }
        CP16(sbase + (CHW + r*36 + q*4)*4, B + (size_t)brow*Hsz + ck*64 + q*8);
    }
    CPCOMMIT();
}

__device__ __forceinline__ void compute_chunk(uint32_t stg,
    float acc[4][4][4], int lane, int wm, int wn)
{
    int laneA_r = lane & 15;
    int laneA_c = (lane >> 4) * 4;
    int laneB_r = (lane & 7) + ((lane >> 4) << 3);
    int laneB_c = ((lane >> 3) & 1) * 4;
    #pragma unroll
    for (int ks = 0; ks < 4; ks++) {
        int kw = ks*8;
        uint32_t ah[4][4], bh[2][4];
        #pragma unroll
        for (int mt = 0; mt < 4; mt++) {
            uint32_t aw = (uint32_t)(wm*64 + mt*16 + laneA_r)*36 + kw + laneA_c;
            LDSM4(ah[mt], stg + aw*4);
        }
        #pragma unroll
        for (int np = 0; np < 2; np++) {
            uint32_t bw = (uint32_t)(wn*32 + np*16 + laneB_r)*36 + kw + laneB_c;
            LDSM4(bh[np], stg + (CHW + bw)*4);
        }
        #pragma unroll
        for (int mt = 0; mt < 4; mt++)
        #pragma unroll
        for (int nt = 0; nt < 4; nt++)
            mma16816(acc[mt][nt], ah[mt], &bh[nt>>1][(nt&1)*2]);
    }
}

// cmode: 0 fp32 row-major out; 1 xgT [t][u][b][g]; 2 E' [tok][u][g]
__global__ void __launch_bounds__(256)
gemm_mma(const __half* __restrict__ A, const __half* __restrict__ B,
         const float* __restrict__ br1, const float* __restrict__ br2,
         const float* __restrict__ bcn, void* __restrict__ Cv,
         int Ntot, int bmap, int mx, int cmode)
{
    extern __shared__ uint32_t sm[];
    uint32_t sbase = smem_u32(sm);
    int tid = threadIdx.x, lane = tid & 31, wid = tid >> 5;
    int wm = wid >> 2, wn = wid & 3;
    int bm = mx ? blockIdx.x : blockIdx.y;
    int bn = mx ? blockIdx.y : blockIdx.x;
    int m0 = cmode ? bm*32 : bm*128;
    int n0 = bn*128;
    int amap = (cmode != 0);

    float acc[4][4][4];
    #pragma unroll
    for (int a = 0; a < 4; a++)
    #pragma unroll
    for (int b = 0; b < 4; b++)
    #pragma unroll
    for (int cc = 0; cc < 4; cc++) acc[a][b][cc] = 0.f;

    load_chunk(sbase, A, B, m0, n0, 0, bmap, amap, tid);
    int st = 0, nst = 1;
    for (int k = 0; k < 8; k++) {
        if (k < 7) {
            load_chunk(sbase + nst*STW*4, A, B, m0, n0, k+1, bmap, amap, tid);
            CPWAIT(1);
        } else {
            CPWAIT(0);
        }
        __syncthreads();
        compute_chunk(sbase + st*STW*4, acc, lane, wm, wn);
        st = nst; nst = (nst + 1 == 3) ? 0 : nst + 1;
    }

    if (cmode) {
        // ---- transpose epilogue: SMEM [ul(32)][cloc(128,pad132)][g(4)] halves ----
        __syncthreads();
        __half* sx = (__half*)sm;
        #pragma unroll
        for (int mt = 0; mt < 4; mt++) {
            #pragma unroll
            for (int half = 0; half < 2; half++) {
                int rloc = wm*64 + mt*16 + (lane >> 2) + half*8;
                int g = rloc >> 5, ul = rloc & 31;
                int nrow = (g << 9) + m0 + ul;
                float rb = br1 ? (br1[nrow] + br2[nrow]) : 0.f;
                #pragma unroll
                for (int nt = 0; nt < 4; nt++) {
                    int cloc = wn*32 + nt*8 + (lane & 3)*2;
                    sx[(ul*132 + cloc)*4 + g]     = __float2half_rn(acc[mt][nt][half*2+0] + rb);
                    sx[(ul*132 + cloc + 1)*4 + g] = __float2half_rn(acc[mt][nt][half*2+1] + rb);
                }
            }
        }
        __syncthreads();
        if (cmode == 1) {
            int t = n0 >> 9, bwin = n0 & 511;
            #pragma unroll
            for (int i = tid; i < 4096; i += 256) {
                int ul = i >> 7, bl = i & 127;
                uint2 v = *(uint2*)&sx[(ul*132 + bl)*4];
                *(uint2*)((__half*)Cv + (((size_t)t*512 + m0 + ul)*512 + bwin + bl)*4) = v;
            }
        } else {
            // E' layout: [tok][u][g]
            #pragma unroll
            for (int i = tid; i < 4096; i += 256) {
                int tkl = i >> 5, ul = i & 31;
                uint2 v = *(uint2*)&sx[(ul*132 + tkl)*4];
                *(uint2*)((__half*)Cv + (((size_t)(n0 + tkl))*512 + m0 + ul)*4) = v;
            }
        }
        return;
    }

    #pragma unroll
    for (int mt = 0; mt < 4; mt++) {
        #pragma unroll
        for (int half = 0; half < 2; half++) {
            int m = m0 + wm*64 + mt*16 + (lane >> 2) + half*8;
            float rb = br1 ? (br1[m] + br2[m]) : 0.f;
            #pragma unroll
            for (int nt = 0; nt < 4; nt++) {
                int c = n0 + wn*32 + nt*8 + (lane & 3)*2;
                float v0 = acc[mt][nt][half*2+0] + rb;
                float v1 = acc[mt][nt][half*2+1] + rb;
                if (bcn) { v0 += bcn[c]; v1 += bcn[c+1]; }
                *(float2*)((float*)Cv + (size_t)m*Ntot + c) = make_float2(v0, v1);
            }
        }
    }
}

// ============ persistent LSTM recurrence ============
#define PS_SMEM 129536
__device__ __forceinline__ int WOFFf(int ck,int r){ return (ck*64 + r)*36; }
__device__ __forceinline__ int HOFFf(int st,int r){ return 18432 + (st*128 + r)*36; }

__global__ void reset_flags(){ int i = threadIdx.x; if (i < 32) ((unsigned*)g_flag)[i] = 0u; }

// mode 0: layer 0 — gate inputs gathered from E' + rank-1 y term (register-resident)
// mode 1: layer 1 — gate inputs read from xgT [t][u][b][g]
__global__ void __launch_bounds__(256,1)
lstm_persist(int mode, const __half* __restrict__ xg,
             const __half* __restrict__ Ep,
             const float* __restrict__ wyv, const float* __restrict__ cbv,
             const int* __restrict__ xtok, const float* __restrict__ yv,
             const __half* __restrict__ W,
             __half* __restrict__ h0, __half* __restrict__ h1,
             __half* __restrict__ seq)
{
    extern __shared__ uint32_t sm[];
    uint32_t sb = smem_u32(sm);
    int tid = threadIdx.x, lane = tid & 31, w = tid >> 5;
    int laneR = lane >> 2, laneC = lane & 3;
    int u0 = blockIdx.x * 16;
    int b0 = blockIdx.y * 128;
    int gid = blockIdx.y;
    int myck = u0 >> 6;

    int laneA_r = lane & 15;
    int laneA_c = (lane >> 4) * 4;
    int laneB_r = (lane & 7) + ((lane >> 4) << 3);
    int laneB_c = ((lane >> 3) & 1) * 4;

    // ---- persistent W tile ----
    for (int i = tid; i < 4096; i += 256) {
        int ck = i >> 9, rem = i & 511;
        int r = rem >> 3, q = rem & 7;
        int g = r >> 4, ul = r & 15;
        CP16(sb + (WOFFf(ck,r) + q*4)*4,
             W + ((size_t)(g*Hsz + u0 + ul))*Hsz + ck*64 + q*8);
    }
    CPCOMMIT(); CPWAIT(0);
    __syncthreads();

    // ---- mode 0: per-thread constant y-conditioning term ----
    float ybase[2][16];
    if (mode == 0) {
        #pragma unroll
        for (int half = 0; half < 2; half++) {
            int b = b0 + w*16 + laneR + half*8;
            float yy = yv[b];
            #pragma unroll
            for (int uh = 0; uh < 2; uh++)
            #pragma unroll
            for (int du = 0; du < 2; du++) {
                int u = u0 + laneC*2 + uh*8 + du;
                float4 wv = *(const float4*)(wyv + u*4);
                float4 cv = *(const float4*)(cbv + u*4);
                ybase[half][uh*8+du*4+0] = yy*wv.x + cv.x;
                ybase[half][uh*8+du*4+1] = yy*wv.y + cv.y;
                ybase[half][uh*8+du*4+2] = yy*wv.z + cv.z;
                ybase[half][uh*8+du*4+3] = yy*wv.w + cv.w;
            }
        }
    }

    __half* hb[2] = {h0, h1};
    float creg[2][2][2];
    #pragma unroll
    for (int a = 0; a < 2; a++)
    #pragma unroll
    for (int b = 0; b < 2; b++) { creg[a][b][0] = 0.f; creg[a][b][1] = 0.f; }

    for (int t = 0; t < Tsz; t++) {
        const __half* Hc = hb[t & 1];
        __half* Nx = hb[(t+1) & 1];
        unsigned tgt = 4u * (unsigned)t;

        float xv[2][16];
        if (mode == 0) {
            #pragma unroll
            for (int half = 0; half < 2; half++) {
                int b = b0 + w*16 + laneR + half*8;
                int tok = (t == 0) ? Vsz : xtok[b*Tsz + t - 1];
                #pragma unroll
                for (int uh = 0; uh < 2; uh++) {
                    int u = u0 + laneC*2 + uh*8;
                    uint4 v = *(const uint4*)(Ep + ((size_t)tok*Hsz + u)*4);
                    __half2 p0 = *(__half2*)&v.x, p1 = *(__half2*)&v.y;
                    __half2 p2 = *(__half2*)&v.z, p3 = *(__half2*)&v.w;
                    xv[half][uh*8+0] = __half2float(p0.x) + ybase[half][uh*8+0];
                    xv[half][uh*8+1] = __half2float(p0.y) + ybase[half][uh*8+1];
                    xv[half][uh*8+2] = __half2float(p1.x) + ybase[half][uh*8+2];
                    xv[half][uh*8+3] = __half2float(p1.y) + ybase[half][uh*8+3];
                    xv[half][uh*8+4] = __half2float(p2.x) + ybase[half][uh*8+4];
                    xv[half][uh*8+5] = __half2float(p2.y) + ybase[half][uh*8+5];
                    xv[half][uh*8+6] = __half2float(p3.x) + ybase[half][uh*8+6];
                    xv[half][uh*8+7] = __half2float(p3.y) + ybase[half][uh*8+7];
                }
            }
        } else {
            const __half* xgt = xg + (size_t)t*G4*Bsz;
            #pragma unroll
            for (int half = 0; half < 2; half++) {
                int b = b0 + w*16 + laneR + half*8;
                #pragma unroll
                for (int uh = 0; uh < 2; uh++)
                #pragma unroll
                for (int du = 0; du < 2; du++) {
                    int u = u0 + laneC*2 + uh*8 + du;
                    uint2 v = *(const uint2*)(xgt + ((size_t)u*512 + b)*4);
                    __half2 p0 = *(__half2*)&v.x;
                    __half2 p1 = *(__half2*)&v.y;
                    xv[half][uh*8+du*4+0] = __half2float(p0.x);
                    xv[half][uh*8+du*4+1] = __half2float(p0.y);
                    xv[half][uh*8+du*4+2] = __half2float(p1.x);
                    xv[half][uh*8+du*4+3] = __half2float(p1.y);
                }
            }
        }

        float acc[8][4];
        #pragma unroll
        for (int i = 0; i < 8; i++)
        #pragma unroll
        for (int j = 0; j < 4; j++) acc[i][j] = 0.f;

        if (t > 0) {
            auto wait_ck = [&](int ck){
                unsigned v;
                do { asm volatile("ld.acquire.gpu.global.u32 %0, [%1];"
                                  : "=r"(v) : "l"(&g_flag[gid][ck])); } while (v < tgt);
            };
            auto ldh = [&](int ck, int st){
                #pragma unroll
                for (int i = tid; i < 1024; i += 256) {
                    int r = i >> 3, q = i & 7;
                    CP16(sb + (HOFFf(st,r) + q*4)*4,
                         Hc + (size_t)(b0 + r)*Hsz + ck*64 + q*8);
                }
                CPCOMMIT();
            };

            wait_ck(0);
            ldh(0, 0);
            int st = 0, nst = 1;
            for (int ck = 0; ck < 8; ck++) {
                if (ck < 7) { wait_ck(ck+1); ldh(ck+1, nst); CPWAIT(1); }
                else        { CPWAIT(0); }
                __syncthreads();
                #pragma unroll
                for (int ks = 0; ks < 4; ks++) {
                    int kw = ks*8;
                    uint32_t ah[4], bh[4][4];
                    uint32_t aw = (uint32_t)(HOFFf(st, w*16 + laneA_r)) + kw + laneA_c;
                    LDSM4(ah, sb + aw*4);
                    #pragma unroll
                    for (int np = 0; np < 4; np++) {
                        uint32_t bw = (uint32_t)(WOFFf(ck, np*16 + laneB_r)) + kw + laneB_c;
                        LDSM4(bh[np], sb + bw*4);
                    }
                    #pragma unroll
                    for (int nt = 0; nt < 8; nt++)
                        mma16816(acc[nt], ah, &bh[nt>>1][(nt&1)*2]);
                }
                st = nst; nst = (nst + 1 == 3) ? 0 : nst + 1;
            }
        }

        // epilogue: gates + state update (c in registers)
        #pragma unroll
        for (int half = 0; half < 2; half++) {
            int b = b0 + w*16 + laneR + half*8;
            #pragma unroll
            for (int uh = 0; uh < 2; uh++) {
                float hn[2];
                #pragma unroll
                for (int du = 0; du < 2; du++) {
                    int q = half*2 + du;
                    float gi = acc[0*2+uh][q] + xv[half][uh*8+du*4+0];
                    float gf = acc[1*2+uh][q] + xv[half][uh*8+du*4+1];
                    float gg = acc[2*2+uh][q] + xv[half][uh*8+du*4+2];
                    float go = acc[3*2+uh][q] + xv[half][uh*8+du*4+3];
                    float is = 1.f/(1.f + __expf(-gi));
                    float fs = 1.f/(1.f + __expf(-gf));
                    float os = 1.f/(1.f + __expf(-go));
                    float gt = tanhf(gg);
                    float cn = fs*creg[half][uh][du] + is*gt;
                    creg[half][uh][du] = cn;
                    hn[du] = os*tanhf(cn);
                }
                int u2 = u0 + laneC*2 + uh*8;
                __half2 hp;
                hp.x = __float2half_rn(hn[0]);
                hp.y = __float2half_rn(hn[1]);
                *(__half2*)(Nx + (size_t)b*Hsz + u2) = hp;
                *(__half2*)(seq + ((size_t)b*Tsz + t)*Hsz + u2) = hp;
            }
        }

        if (t < Tsz - 1) {
            __threadfence();
            __syncthreads();
            if (tid == 0) atomicAdd(&g_flag[gid][myck], 1u);
        }
    }
}

// ---------------- small kernels ----------------
__global__ void conv_kernel(const float* __restrict__ s, __half* __restrict__ h, int n4){
    int i = blockIdx.x*blockDim.x + threadIdx.x;
    if (i < n4) {
        float4 v = ((const float4*)s)[i];
        __half2 a, b;
        a.x = __float2half_rn(v.x); a.y = __float2half_rn(v.y);
        b.x = __float2half_rn(v.z); b.y = __float2half_rn(v.w);
        ((__half2*)h)[i*2]   = a;
        ((__half2*)h)[i*2+1] = b;
    }
}
// wy[u*4+g] = Wih0[n]·yW ; cb[u*4+g] = Wih0[n]·yb + bih0[n] + bhh0[n],  n = g*512+u
__global__ void prep_y(const float* __restrict__ Wih, const float* __restrict__ yW,
                       const float* __restrict__ yb, const float* __restrict__ bih,
                       const float* __restrict__ bhh,
                       float* __restrict__ wyv, float* __restrict__ cbv)
{
    int n = blockIdx.x*8 + (threadIdx.x >> 5);
    int lane = threadIdx.x & 31;
    const float* wr = Wih + (size_t)n*Hsz;
    float s1 = 0.f, s2 = 0.f;
    for (int k = lane; k < Hsz; k += 32) { float wv = wr[k]; s1 += wv*yW[k]; s2 += wv*yb[k]; }
    #pragma unroll
    for (int o = 16; o; o >>= 1) {
        s1 += __shfl_down_sync(0xFFFFFFFFu, s1, o);
        s2 += __shfl_down_sync(0xFFFFFFFFu, s2, o);
    }
    if (lane == 0) {
        int g = n >> 9, u = n & 511;
        wyv[u*4+g] = s1;
        cbv[u*4+g] = s2 + bih[n] + bhh[n];
    }
}

// ---------------- launch ----------------
extern "C" void kernel_launch(void* const* d_in, const int* in_sizes, int n_in,
                              void* d_out, int out_size)
{
    const int*   x    = (const int*)  d_in[0];
    const float* y    = (const float*)d_in[1];
    const float* emb  = (const float*)d_in[2];
    const float* yW   = (const float*)d_in[3];
    const float* yb   = (const float*)d_in[4];
    const float* Wih  = (const float*)d_in[5];
    const float* Whh  = (const float*)d_in[6];
    const float* bih  = (const float*)d_in[7];
    const float* bhh  = (const float*)d_in[8];
    const float* decW = (const float*)d_in[9];
    const float* decb = (const float*)d_in[10];
    float* out = (float*)d_out;

    __half *seq, *Wih_c, *Whh_c, *dW_c, *h0, *h1, *xgT, *embp, *Ep;
    float *wyv, *cbv;
    cudaGetSymbolAddress((void**)&seq,   g_seq);
    cudaGetSymbolAddress((void**)&xgT,   g_xgT);
    cudaGetSymbolAddress((void**)&h0,    g_h0);
    cudaGetSymbolAddress((void**)&h1,    g_h1);
    cudaGetSymbolAddress((void**)&Wih_c, g_Wih);
    cudaGetSymbolAddress((void**)&Whh_c, g_Whh);
    cudaGetSymbolAddress((void**)&dW_c,  g_dW);
    cudaGetSymbolAddress((void**)&embp,  g_embp);
    cudaGetSymbolAddress((void**)&Ep,    g_Ep);
    cudaGetSymbolAddress((void**)&wyv,   g_wyv);
    cudaGetSymbolAddress((void**)&cbv,   g_cbv);

    cudaFuncSetAttribute(gemm_mma, cudaFuncAttributeMaxDynamicSharedMemorySize, SMEMB);
    cudaFuncSetAttribute(lstm_persist, cudaFuncAttributeMaxDynamicSharedMemorySize, PS_SMEM);

    const int nW4 = 2*G4*Hsz/4;
    conv_kernel<<<(nW4+255)/256, 256>>>(Wih, Wih_c, nW4);
    conv_kernel<<<(nW4+255)/256, 256>>>(Whh, Whh_c, nW4);
    conv_kernel<<<(Vsz*Hsz/4+255)/256, 256>>>(decW, dW_c, Vsz*Hsz/4);
    conv_kernel<<<(513*Hsz/4+255)/256, 256>>>(emb, embp, 513*Hsz/4);
    prep_y<<<G4/8, 256>>>(Wih, yW, yb, bih, bhh, wyv, cbv);

    // E' = Wih0 · embp^T  -> [tok][u][g] fp16
    gemm_mma<<<dim3(16, TOKP/128), 256, SMEMB>>>(
        Wih_c, embp, nullptr, nullptr, nullptr, Ep, TOKP, 0, 1, 2);

    // ---- layer 0: recurrence with E' gather (no xg GEMM) ----
    reset_flags<<<1, 32>>>();
    lstm_persist<<<dim3(Hsz/16, Bsz/128), 256, PS_SMEM>>>(
        0, xgT, Ep, wyv, cbv, x, y, Whh_c, h0, h1, seq);

    // ---- layer 1: xg GEMM + recurrence ----
    gemm_mma<<<dim3(16, NBT/128), 256, SMEMB>>>(
        Wih_c + (size_t)G4*Hsz, seq, bih + G4, bhh + G4, nullptr, xgT, NBT, 1, 1, 1);

    reset_flags<<<1, 32>>>();
    lstm_persist<<<dim3(Hsz/16, Bsz/128), 256, PS_SMEM>>>(
        1, xgT, Ep, wyv, cbv, x, y, Whh_c + (size_t)G4*Hsz, h0, h1, seq);

    // ---- decoder ----
    gemm_mma<<<dim3(Vsz/128, NBT/128), 256, SMEMB>>>(
        seq, dW_c, nullptr, nullptr, decb, out, Vsz, 0, 0, 0);
}

// round 13
// speedup vs baseline: 1.3748x; 1.0816x over previous
#include <cuda_runtime.h>
#include <cuda_fp16.h>
#include <stdint.h>
#include <math.h>

#define Bsz 512
#define Tsz 128
#define Hsz 512
#define Vsz 512
#define NBT 65536
#define G4  2048
#define TOKP 640   // padded token count (513 -> 640)

// ---------------- device scratch ----------------
__device__ __align__(128) __half g_seq[(size_t)NBT*Hsz];
__device__ __align__(128) __half g_xgT[(size_t)Tsz*G4*Bsz];   // [t][u][b][g] fp16 (layer 1 only)
__device__ __align__(128) __half g_h0[Bsz*Hsz], g_h1[Bsz*Hsz];
__device__ __align__(128) __half g_Wih[2*(size_t)G4*Hsz];
__device__ __align__(128) __half g_Whh[2*(size_t)G4*Hsz];
__device__ __align__(128) __half g_dW[(size_t)Vsz*Hsz];
__device__ __align__(128) __half g_embp[TOKP*Hsz];            // padded fp16 emb
__device__ __align__(128) __half g_Ep[(size_t)TOKP*Hsz*4];    // E' [tok][u][g] fp16
__device__ __align__(128) float  g_wyv[G4], g_cbv[G4];        // [u*4+g] fp32
__device__ unsigned g_flag[4][8];

// ---------------- helpers ----------------
__device__ __forceinline__ uint32_t smem_u32(const void* p){
    uint32_t a; asm("{ .reg .u64 t; cvta.to.shared.u64 t, %1; cvt.u32.u64 %0, t; }" : "=r"(a) : "l"(p)); return a;
}
#define CP16(dst, src) asm volatile("cp.async.cg.shared.global [%0], [%1], 16;" :: "r"(dst), "l"(src))
#define CPCOMMIT()     asm volatile("cp.async.commit_group;" ::: "memory")
#define CPWAIT(n)      asm volatile("cp.async.wait_group %0;" :: "n"(n) : "memory")
#define LDSM4(r, a) asm volatile("ldmatrix.sync.aligned.m8n8.x4.shared.b16 {%0,%1,%2,%3}, [%4];" \
    : "=r"((r)[0]),"=r"((r)[1]),"=r"((r)[2]),"=r"((r)[3]) : "r"(a))

__device__ __forceinline__ void mma16816(float* d, const uint32_t* a, const uint32_t* b){
    asm volatile("mma.sync.aligned.m16n8k16.row.col.f32.f16.f16.f32 "
        "{%0,%1,%2,%3}, {%4,%5,%6,%7}, {%8,%9}, {%0,%1,%2,%3};"
        : "+f"(d[0]), "+f"(d[1]), "+f"(d[2]), "+f"(d[3])
        : "r"(a[0]), "r"(a[1]), "r"(a[2]), "r"(a[3]), "r"(b[0]), "r"(b[1]));
}

// fast transcendentals (MUFU ex2 + rcp; ~1e-7 rel err, correct saturation)
__device__ __forceinline__ float fast_ex2(float x){ float r; asm("ex2.approx.f32 %0, %1;" : "=f"(r) : "f"(x)); return r; }
__device__ __forceinline__ float fast_rcp(float x){ float r; asm("rcp.approx.f32 %0, %1;" : "=f"(r) : "f"(x)); return r; }
__device__ __forceinline__ float fsig(float x){ return fast_rcp(1.f + fast_ex2(-1.4426950408889634f*x)); }
__device__ __forceinline__ float ftanh(float x){ return 2.f*fast_rcp(1.f + fast_ex2(-2.885390081777927f*x)) - 1.f; }

// ============ generic FF GEMM (fp16 operands, fp32 accum) ============
#define CHW 4608
#define STW 9216
#define SMEMB 110592   // 3 stages

__device__ __forceinline__ void load_chunk(uint32_t sbase,
    const __half* __restrict__ A, const __half* __restrict__ B,
    int m0, int n0, int ck, int bmap, int amap, int tid)
{
    #pragma unroll
    for (int i = tid; i < 1024; i += 256) {
        int r = i >> 3, q = i & 7;
        int arow = amap ? (((r >> 5) << 9) + m0 + (r & 31)) : (m0 + r);
        CP16(sbase + (r*36 + q*4)*4, A + (size_t)arow*Hsz + ck*64 + q*8);
    }
    #pragma unroll
    for (int i = tid; i < 1024; i += 256) {
        int r = i >> 3, q = i & 7;
        int brow;
        if (bmap == 0)      brow = n0 + r;
        else                { int c = n0 + r; brow = (c & 511)*Tsz + (c >> 9); }
        CP16(sbase + (CHW + r*36 + q*4)*4, B + (size_t)brow*Hsz + ck*64 + q*8);
    }
    CPCOMMIT();
}

__device__ __forceinline__ void compute_chunk(uint32_t stg,
    float acc[4][4][4], int lane, int wm, int wn)
{
    int laneA_r = lane & 15;
    int laneA_c = (lane >> 4) * 4;
    int laneB_r = (lane & 7) + ((lane >> 4) << 3);
    int laneB_c = ((lane >> 3) & 1) * 4;
    #pragma unroll
    for (int ks = 0; ks < 4; ks++) {
        int kw = ks*8;
        uint32_t ah[4][4], bh[2][4];
        #pragma unroll
        for (int mt = 0; mt < 4; mt++) {
            uint32_t aw = (uint32_t)(wm*64 + mt*16 + laneA_r)*36 + kw + laneA_c;
            LDSM4(ah[mt], stg + aw*4);
        }
        #pragma unroll
        for (int np = 0; np < 2; np++) {
            uint32_t bw = (uint32_t)(wn*32 + np*16 + laneB_r)*36 + kw + laneB_c;
            LDSM4(bh[np], stg + (CHW + bw)*4);
        }
        #pragma unroll
        for (int mt = 0; mt < 4; mt++)
        #pragma unroll
        for (int nt = 0; nt < 4; nt++)
            mma16816(acc[mt][nt], ah[mt], &bh[nt>>1][(nt&1)*2]);
    }
}

// cmode: 0 fp32 row-major out; 1 xgT [t][u][b][g]; 2 E' [tok][u][g]
__global__ void __launch_bounds__(256,2)
gemm_mma(const __half* __restrict__ A, const __half* __restrict__ B,
         const float* __restrict__ br1, const float* __restrict__ br2,
         const float* __restrict__ bcn, void* __restrict__ Cv,
         int Ntot, int bmap, int mx, int cmode)
{
    extern __shared__ uint32_t sm[];
    uint32_t sbase = smem_u32(sm);
    int tid = threadIdx.x, lane = tid & 31, wid = tid >> 5;
    int wm = wid >> 2, wn = wid & 3;
    int bm = mx ? blockIdx.x : blockIdx.y;
    int bn = mx ? blockIdx.y : blockIdx.x;
    int m0 = cmode ? bm*32 : bm*128;
    int n0 = bn*128;
    int amap = (cmode != 0);

    float acc[4][4][4];
    #pragma unroll
    for (int a = 0; a < 4; a++)
    #pragma unroll
    for (int b = 0; b < 4; b++)
    #pragma unroll
    for (int cc = 0; cc < 4; cc++) acc[a][b][cc] = 0.f;

    load_chunk(sbase, A, B, m0, n0, 0, bmap, amap, tid);
    int st = 0, nst = 1;
    for (int k = 0; k < 8; k++) {
        if (k < 7) {
            load_chunk(sbase + nst*STW*4, A, B, m0, n0, k+1, bmap, amap, tid);
            CPWAIT(1);
        } else {
            CPWAIT(0);
        }
        __syncthreads();
        compute_chunk(sbase + st*STW*4, acc, lane, wm, wn);
        st = nst; nst = (nst + 1 == 3) ? 0 : nst + 1;
    }

    if (cmode) {
        // ---- transpose epilogue: SMEM [ul(32)][cloc(128,pad132)][g(4)] halves ----
        __syncthreads();
        __half* sx = (__half*)sm;
        #pragma unroll
        for (int mt = 0; mt < 4; mt++) {
            #pragma unroll
            for (int half = 0; half < 2; half++) {
                int rloc = wm*64 + mt*16 + (lane >> 2) + half*8;
                int g = rloc >> 5, ul = rloc & 31;
                int nrow = (g << 9) + m0 + ul;
                float rb = br1 ? (br1[nrow] + br2[nrow]) : 0.f;
                #pragma unroll
                for (int nt = 0; nt < 4; nt++) {
                    int cloc = wn*32 + nt*8 + (lane & 3)*2;
                    sx[(ul*132 + cloc)*4 + g]     = __float2half_rn(acc[mt][nt][half*2+0] + rb);
                    sx[(ul*132 + cloc + 1)*4 + g] = __float2half_rn(acc[mt][nt][half*2+1] + rb);
                }
            }
        }
        __syncthreads();
        if (cmode == 1) {
            int t = n0 >> 9, bwin = n0 & 511;
            #pragma unroll
            for (int i = tid; i < 4096; i += 256) {
                int ul = i >> 7, bl = i & 127;
                uint2 v = *(uint2*)&sx[(ul*132 + bl)*4];
                *(uint2*)((__half*)Cv + (((size_t)t*512 + m0 + ul)*512 + bwin + bl)*4) = v;
            }
        } else {
            #pragma unroll
            for (int i = tid; i < 4096; i += 256) {
                int tkl = i >> 5, ul = i & 31;
                uint2 v = *(uint2*)&sx[(ul*132 + tkl)*4];
                *(uint2*)((__half*)Cv + (((size_t)(n0 + tkl))*512 + m0 + ul)*4) = v;
            }
        }
        return;
    }

    #pragma unroll
    for (int mt = 0; mt < 4; mt++) {
        #pragma unroll
        for (int half = 0; half < 2; half++) {
            int m = m0 + wm*64 + mt*16 + (lane >> 2) + half*8;
            float rb = br1 ? (br1[m] + br2[m]) : 0.f;
            #pragma unroll
            for (int nt = 0; nt < 4; nt++) {
                int c = n0 + wn*32 + nt*8 + (lane & 3)*2;
                float v0 = acc[mt][nt][half*2+0] + rb;
                float v1 = acc[mt][nt][half*2+1] + rb;
                if (bcn) { v0 += bcn[c]; v1 += bcn[c+1]; }
                *(float2*)((float*)Cv + (size_t)m*Ntot + c) = make_float2(v0, v1);
            }
        }
    }
}

// ============ persistent LSTM recurrence ============
#define PS_SMEM 129536
__device__ __forceinline__ int WOFFf(int ck,int r){ return (ck*64 + r)*36; }
__device__ __forceinline__ int HOFFf(int st,int r){ return 18432 + (st*128 + r)*36; }

__global__ void reset_flags(){ int i = threadIdx.x; if (i < 32) ((unsigned*)g_flag)[i] = 0u; }

// mode 0: layer 0 — gate inputs gathered from E' + rank-1 y term (register-resident)
// mode 1: layer 1 — gate inputs read from xgT [t][u][b][g]
__global__ void __launch_bounds__(256,1)
lstm_persist(int mode, const __half* __restrict__ xg,
             const __half* __restrict__ Ep,
             const float* __restrict__ wyv, const float* __restrict__ cbv,
             const int* __restrict__ xtok, const float* __restrict__ yv,
             const __half* __restrict__ W,
             __half* __restrict__ h0, __half* __restrict__ h1,
             __half* __restrict__ seq)
{
    extern __shared__ uint32_t sm[];
    uint32_t sb = smem_u32(sm);
    int tid = threadIdx.x, lane = tid & 31, w = tid >> 5;
    int laneR = lane >> 2, laneC = lane & 3;
    int u0 = blockIdx.x * 16;
    int b0 = blockIdx.y * 128;
    int gid = blockIdx.y;
    int myck = u0 >> 6;

    int laneA_r = lane & 15;
    int laneA_c = (lane >> 4) * 4;
    int laneB_r = (lane & 7) + ((lane >> 4) << 3);
    int laneB_c = ((lane >> 3) & 1) * 4;

    // ---- persistent W tile ----
    for (int i = tid; i < 4096; i += 256) {
        int ck = i >> 9, rem = i & 511;
        int r = rem >> 3, q = rem & 7;
        int g = r >> 4, ul = r & 15;
        CP16(sb + (WOFFf(ck,r) + q*4)*4,
             W + ((size_t)(g*Hsz + u0 + ul))*Hsz + ck*64 + q*8);
    }
    CPCOMMIT(); CPWAIT(0);
    __syncthreads();

    // ---- mode 0: per-thread constant y-conditioning term ----
    float ybase[2][16];
    if (mode == 0) {
        #pragma unroll
        for (int half = 0; half < 2; half++) {
            int b = b0 + w*16 + laneR + half*8;
            float yy = yv[b];
            #pragma unroll
            for (int uh = 0; uh < 2; uh++)
            #pragma unroll
            for (int du = 0; du < 2; du++) {
                int u = u0 + laneC*2 + uh*8 + du;
                float4 wv = *(const float4*)(wyv + u*4);
                float4 cv = *(const float4*)(cbv + u*4);
                ybase[half][uh*8+du*4+0] = yy*wv.x + cv.x;
                ybase[half][uh*8+du*4+1] = yy*wv.y + cv.y;
                ybase[half][uh*8+du*4+2] = yy*wv.z + cv.z;
                ybase[half][uh*8+du*4+3] = yy*wv.w + cv.w;
            }
        }
    }

    __half* hb[2] = {h0, h1};
    float creg[2][2][2];
    #pragma unroll
    for (int a = 0; a < 2; a++)
    #pragma unroll
    for (int b = 0; b < 2; b++) { creg[a][b][0] = 0.f; creg[a][b][1] = 0.f; }

    for (int t = 0; t < Tsz; t++) {
        const __half* Hc = hb[t & 1];
        __half* Nx = hb[(t+1) & 1];
        unsigned tgt = 4u * (unsigned)t;

        float xv[2][16];
        if (mode == 0) {
            #pragma unroll
            for (int half = 0; half < 2; half++) {
                int b = b0 + w*16 + laneR + half*8;
                int tok = (t == 0) ? Vsz : xtok[b*Tsz + t - 1];
                #pragma unroll
                for (int uh = 0; uh < 2; uh++) {
                    int u = u0 + laneC*2 + uh*8;
                    uint4 v = *(const uint4*)(Ep + ((size_t)tok*Hsz + u)*4);
                    __half2 p0 = *(__half2*)&v.x, p1 = *(__half2*)&v.y;
                    __half2 p2 = *(__half2*)&v.z, p3 = *(__half2*)&v.w;
                    xv[half][uh*8+0] = __half2float(p0.x) + ybase[half][uh*8+0];
                    xv[half][uh*8+1] = __half2float(p0.y) + ybase[half][uh*8+1];
                    xv[half][uh*8+2] = __half2float(p1.x) + ybase[half][uh*8+2];
                    xv[half][uh*8+3] = __half2float(p1.y) + ybase[half][uh*8+3];
                    xv[half][uh*8+4] = __half2float(p2.x) + ybase[half][uh*8+4];
                    xv[half][uh*8+5] = __half2float(p2.y) + ybase[half][uh*8+5];
                    xv[half][uh*8+6] = __half2float(p3.x) + ybase[half][uh*8+6];
                    xv[half][uh*8+7] = __half2float(p3.y) + ybase[half][uh*8+7];
                }
            }
        } else {
            const __half* xgt = xg + (size_t)t*G4*Bsz;
            #pragma unroll
            for (int half = 0; half < 2; half++) {
                int b = b0 + w*16 + laneR + half*8;
                #pragma unroll
                for (int uh = 0; uh < 2; uh++)
                #pragma unroll
                for (int du = 0; du < 2; du++) {
                    int u = u0 + laneC*2 + uh*8 + du;
                    uint2 v = *(const uint2*)(xgt + ((size_t)u*512 + b)*4);
                    __half2 p0 = *(__half2*)&v.x;
                    __half2 p1 = *(__half2*)&v.y;
                    xv[half][uh*8+du*4+0] = __half2float(p0.x);
                    xv[half][uh*8+du*4+1] = __half2float(p0.y);
                    xv[half][uh*8+du*4+2] = __half2float(p1.x);
                    xv[half][uh*8+du*4+3] = __half2float(p1.y);
                }
            }
        }

        float acc[8][4];
        #pragma unroll
        for (int i = 0; i < 8; i++)
        #pragma unroll
        for (int j = 0; j < 4; j++) acc[i][j] = 0.f;

        if (t > 0) {
            auto wait_ck = [&](int ck){
                unsigned v;
                do { asm volatile("ld.acquire.gpu.global.u32 %0, [%1];"
                                  : "=r"(v) : "l"(&g_flag[gid][ck])); } while (v < tgt);
            };
            auto ldh = [&](int ck, int st){
                #pragma unroll
                for (int i = tid; i < 1024; i += 256) {
                    int r = i >> 3, q = i & 7;
                    CP16(sb + (HOFFf(st,r) + q*4)*4,
                         Hc + (size_t)(b0 + r)*Hsz + ck*64 + q*8);
                }
                CPCOMMIT();
            };

            wait_ck(0);
            ldh(0, 0);
            int st = 0, nst = 1;
            for (int ck = 0; ck < 8; ck++) {
                if (ck < 7) { wait_ck(ck+1); ldh(ck+1, nst); CPWAIT(1); }
                else        { CPWAIT(0); }
                __syncthreads();
                #pragma unroll
                for (int ks = 0; ks < 4; ks++) {
                    int kw = ks*8;
                    uint32_t ah[4], bh[4][4];
                    uint32_t aw = (uint32_t)(HOFFf(st, w*16 + laneA_r)) + kw + laneA_c;
                    LDSM4(ah, sb + aw*4);
                    #pragma unroll
                    for (int np = 0; np < 4; np++) {
                        uint32_t bw = (uint32_t)(WOFFf(ck, np*16 + laneB_r)) + kw + laneB_c;
                        LDSM4(bh[np], sb + bw*4);
                    }
                    #pragma unroll
                    for (int nt = 0; nt < 8; nt++)
                        mma16816(acc[nt], ah, &bh[nt>>1][(nt&1)*2]);
                }
                st = nst; nst = (nst + 1 == 3) ? 0 : nst + 1;
            }
        }

        // epilogue: gates + state update (c in registers, fast transcendentals)
        #pragma unroll
        for (int half = 0; half < 2; half++) {
            int b = b0 + w*16 + laneR + half*8;
            #pragma unroll
            for (int uh = 0; uh < 2; uh++) {
                float hn[2];
                #pragma unroll
                for (int du = 0; du < 2; du++) {
                    int q = half*2 + du;
                    float gi = acc[0*2+uh][q] + xv[half][uh*8+du*4+0];
                    float gf = acc[1*2+uh][q] + xv[half][uh*8+du*4+1];
                    float gg = acc[2*2+uh][q] + xv[half][uh*8+du*4+2];
                    float go = acc[3*2+uh][q] + xv[half][uh*8+du*4+3];
                    float is = fsig(gi);
                    float fs = fsig(gf);
                    float os = fsig(go);
                    float gt = ftanh(gg);
                    float cn = fs*creg[half][uh][du] + is*gt;
                    creg[half][uh][du] = cn;
                    hn[du] = os*ftanh(cn);
                }
                int u2 = u0 + laneC*2 + uh*8;
                __half2 hp;
                hp.x = __float2half_rn(hn[0]);
                hp.y = __float2half_rn(hn[1]);
                *(__half2*)(Nx + (size_t)b*Hsz + u2) = hp;
                *(__half2*)(seq + ((size_t)b*Tsz + t)*Hsz + u2) = hp;
            }
        }

        if (t < Tsz - 1) {
            __threadfence();
            __syncthreads();
            if (tid == 0) atomicAdd(&g_flag[gid][myck], 1u);
        }
    }
}

// ---------------- small kernels ----------------
__global__ void conv_kernel(const float* __restrict__ s, __half* __restrict__ h, int n4){
    int i = blockIdx.x*blockDim.x + threadIdx.x;
    if (i < n4) {
        float4 v = ((const float4*)s)[i];
        __half2 a, b;
        a.x = __float2half_rn(v.x); a.y = __float2half_rn(v.y);
        b.x = __float2half_rn(v.z); b.y = __float2half_rn(v.w);
        ((__half2*)h)[i*2]   = a;
        ((__half2*)h)[i*2+1] = b;
    }
}
// wy[u*4+g] = Wih0[n]·yW ; cb[u*4+g] = Wih0[n]·yb + bih0[n] + bhh0[n],  n = g*512+u
__global__ void prep_y(const float* __restrict__ Wih, const float* __restrict__ yW,
                       const float* __restrict__ yb, const float* __restrict__ bih,
                       const float* __restrict__ bhh,
                       float* __restrict__ wyv, float* __restrict__ cbv)
{
    int n = blockIdx.x*8 + (threadIdx.x >> 5);
    int lane = threadIdx.x & 31;
    const float* wr = Wih + (size_t)n*Hsz;
    float s1 = 0.f, s2 = 0.f;
    for (int k = lane; k < Hsz; k += 32) { float wv = wr[k]; s1 += wv*yW[k]; s2 += wv*yb[k]; }
    #pragma unroll
    for (int o = 16; o; o >>= 1) {
        s1 += __shfl_down_sync(0xFFFFFFFFu, s1, o);
        s2 += __shfl_down_sync(0xFFFFFFFFu, s2, o);
    }
    if (lane == 0) {
        int g = n >> 9, u = n & 511;
        wyv[u*4+g] = s1;
        cbv[u*4+g] = s2 + bih[n] + bhh[n];
    }
}

// ---------------- launch ----------------
extern "C" void kernel_launch(void* const* d_in, const int* in_sizes, int n_in,
                              void* d_out, int out_size)
{
    const int*   x    = (const int*)  d_in[0];
    const float* y    = (const float*)d_in[1];
    const float* emb  = (const float*)d_in[2];
    const float* yW   = (const float*)d_in[3];
    const float* yb   = (const float*)d_in[4];
    const float* Wih  = (const float*)d_in[5];
    const float* Whh  = (const float*)d_in[6];
    const float* bih  = (const float*)d_in[7];
    const float* bhh  = (const float*)d_in[8];
    const float* decW = (const float*)d_in[9];
    const float* decb = (const float*)d_in[10];
    float* out = (float*)d_out;

    __half *seq, *Wih_c, *Whh_c, *dW_c, *h0, *h1, *xgT, *embp, *Ep;
    float *wyv, *cbv;
    cudaGetSymbolAddress((void**)&seq,   g_seq);
    cudaGetSymbolAddress((void**)&xgT,   g_xgT);
    cudaGetSymbolAddress((void**)&h0,    g_h0);
    cudaGetSymbolAddress((void**)&h1,    g_h1);
    cudaGetSymbolAddress((void**)&Wih_c, g_Wih);
    cudaGetSymbolAddress((void**)&Whh_c, g_Whh);
    cudaGetSymbolAddress((void**)&dW_c,  g_dW);
    cudaGetSymbolAddress((void**)&embp,  g_embp);
    cudaGetSymbolAddress((void**)&Ep,    g_Ep);
    cudaGetSymbolAddress((void**)&wyv,   g_wyv);
    cudaGetSymbolAddress((void**)&cbv,   g_cbv);

    cudaFuncSetAttribute(gemm_mma, cudaFuncAttributeMaxDynamicSharedMemorySize, SMEMB);
    cudaFuncSetAttribute(lstm_persist, cudaFuncAttributeMaxDynamicSharedMemorySize, PS_SMEM);

    const int nW4 = 2*G4*Hsz/4;
    conv_kernel<<<(nW4+255)/256, 256>>>(Wih, Wih_c, nW4);
    conv_kernel<<<(nW4+255)/256, 256>>>(Whh, Whh_c, nW4);
    conv_kernel<<<(Vsz*Hsz/4+255)/256, 256>>>(decW, dW_c, Vsz*Hsz/4);
    conv_kernel<<<(513*Hsz/4+255)/256, 256>>>(emb, embp, 513*Hsz/4);
    prep_y<<<G4/8, 256>>>(Wih, yW, yb, bih, bhh, wyv, cbv);

    // E' = Wih0 · embp^T  -> [tok][u][g] fp16
    gemm_mma<<<dim3(16, TOKP/128), 256, SMEMB>>>(
        Wih_c, embp, nullptr, nullptr, nullptr, Ep, TOKP, 0, 1, 2);

    // ---- layer 0: recurrence with E' gather (no xg GEMM) ----
    reset_flags<<<1, 32>>>();
    lstm_persist<<<dim3(Hsz/16, Bsz/128), 256, PS_SMEM>>>(
        0, xgT, Ep, wyv, cbv, x, y, Whh_c, h0, h1, seq);

    // ---- layer 1: xg GEMM + recurrence ----
    gemm_mma<<<dim3(16, NBT/128), 256, SMEMB>>>(
        Wih_c + (size_t)G4*Hsz, seq, bih + G4, bhh + G4, nullptr, xgT, NBT, 1, 1, 1);

    reset_flags<<<1, 32>>>();
    lstm_persist<<<dim3(Hsz/16, Bsz/128), 256, PS_SMEM>>>(
        1, xgT, Ep, wyv, cbv, x, y, Whh_c + (size_t)G4*Hsz, h0, h1, seq);

    // ---- decoder ----
    gemm_mma<<<dim3(Vsz/128, NBT/128), 256, SMEMB>>>(
        seq, dW_c, nullptr, nullptr, decb, out, Vsz, 0, 0, 0);
}